// round 6
// baseline (speedup 1.0000x reference)
#include <cuda_runtime.h>

#define NWARP 8
#define NTHR  (NWARP*32)

// ---------------------------------------------------------------------------
// Compile-time geometric algebra for Cl(3,0,1), METRIC=(0,1,1,1).
// ---------------------------------------------------------------------------
__host__ __device__ constexpr int ga_popc(int x){ return (x&1)+((x>>1)&1)+((x>>2)&1)+((x>>3)&1); }
__host__ __device__ constexpr int ga_mask(int i){
    return i==0?0: i==1?1: i==2?2: i==3?4: i==4?8: i==5?3: i==6?5: i==7?9:
           i==8?6: i==9?10: i==10?12: i==11?7: i==12?11: i==13?13: i==14?14: 15;
}
__host__ __device__ constexpr int ga_idx(int m){
    return m==0?0: m==1?1: m==2?2: m==4?3: m==8?4: m==3?5: m==5?6: m==9?7:
           m==6?8: m==10?9: m==12?10: m==7?11: m==11?12: m==13?13: m==14?14: 15;
}
__host__ __device__ constexpr int ga_grade(int i){ return ga_popc(ga_mask(i)); }
__host__ __device__ constexpr int ga_csign(int a, int b){
    int s = 0;
    for (int i = 0; i < 4; ++i) if ((b>>i)&1) s += ga_popc(a >> (i+1));
    return (s&1) ? -1 : 1;
}
__host__ __device__ constexpr int ga_dsign(int b){ return ga_csign(ga_mask(b), 15 ^ ga_mask(b)); }

struct GaTabs {
    signed char gs[16][16]; signed char gi[16][16];
    signed char js[16][16]; signed char ja[16][16];
};
__host__ __device__ constexpr GaTabs ga_make(){
    GaTabs t{};
    for (int j = 0; j < 16; ++j)
        for (int k = 0; k < 16; ++k){
            int mj = ga_mask(j), mk = ga_mask(k);
            if (mj & mk & 1){ t.gs[j][k] = 0; t.gi[j][k] = 0; }
            else { t.gs[j][k] = (signed char)ga_csign(mj, mk); t.gi[j][k] = (signed char)ga_idx(mj ^ mk); }
            int jm = 15 ^ mj, km = 15 ^ mk;
            if (jm & km){ t.js[j][k] = 0; t.ja[j][k] = 0; }
            else {
                int im = jm ^ km;
                int s = ga_csign(im, 15 ^ im) * ga_csign(jm, km) * ga_dsign(j) * ga_dsign(k);
                t.js[j][k] = (signed char)s;
                t.ja[j][k] = (signed char)ga_idx(15 ^ im);
            }
        }
    return t;
}

// ---------------------------------------------------------------------------
// packed f32x2 helpers
// ---------------------------------------------------------------------------
typedef unsigned long long u64;
__device__ __forceinline__ u64 pk2(float a, float b){ u64 r; asm("mov.b64 %0,{%1,%2};":"=l"(r):"f"(a),"f"(b)); return r; }
__device__ __forceinline__ void unpk2(u64 v, float& a, float& b){ asm("mov.b64 {%0,%1},%2;":"=f"(a),"=f"(b):"l"(v)); }
__device__ __forceinline__ u64 dup2(float a){ u64 r; asm("mov.b64 %0,{%1,%1};":"=l"(r):"f"(a)); return r; }
__device__ __forceinline__ u64 fma2(u64 a, u64 b, u64 c){ u64 d; asm("fma.rn.f32x2 %0,%1,%2,%3;":"=l"(d):"l"(a),"l"(b),"l"(c)); return d; }
__device__ __forceinline__ u64 mul2(u64 a, u64 b){ u64 d; asm("mul.rn.f32x2 %0,%1,%2;":"=l"(d):"l"(a),"l"(b)); return d; }
__device__ __forceinline__ u64 neg2(u64 a){ return a ^ 0x8000000080000000ull; }

// apply basis map B to packed accumulators (compile-time B)
template<int B>
__device__ __forceinline__ void apply_b2(float wa, float wb, const u64* x2, u64* a0, u64* a1){
    u64 w0 = dup2(wa), w1 = dup2(wb);
    #pragma unroll
    for (int j = 0; j < 16; ++j){
        if (B < 5){
            if (ga_grade(j) == B){ a0[j] = fma2(w0, x2[j], a0[j]); a1[j] = fma2(w1, x2[j], a1[j]); }
        } else {
            if (!(ga_mask(j)&1) && ga_grade(j) == B-5){
                const int jj = ga_idx(ga_mask(j)|1);
                a0[jj] = fma2(w0, x2[j], a0[jj]); a1[jj] = fma2(w1, x2[j], a1[jj]);
            }
        }
    }
}
template<int B>
__device__ __forceinline__ void apply_b1(float wv, const u64* x2, u64* a){
    u64 w = dup2(wv);
    #pragma unroll
    for (int j = 0; j < 16; ++j){
        if (B < 5){
            if (ga_grade(j) == B) a[j] = fma2(w, x2[j], a[j]);
        } else {
            if (!(ga_mask(j)&1) && ga_grade(j) == B-5){
                const int jj = ga_idx(ga_mask(j)|1);
                a[jj] = fma2(w, x2[j], a[jj]);
            }
        }
    }
}

// ---------------------------------------------------------------------------
// smem layout (floats). Staging: per warp 2 packs x 32 rows x 36 floats.
// ---------------------------------------------------------------------------
#define OFF_WMV   0
#define OFF_WS    (OFF_WMV + 18432)
#define OFF_WOM   (OFF_WS  + 4096)
#define OFF_WM2S  (OFF_WOM + 9216)
#define OFF_WS2S  (OFF_WM2S+ 2048)
#define OFF_STG   (OFF_WS2S+ 4096)
#define STGW      2304
#define SMEMF (OFF_STG + NWARP*STGW)   /* 56320 floats = 225.3 KB */

__global__ void __launch_bounds__(NTHR, 1)
fused_kernel(const float* __restrict__ mv, const float* __restrict__ refmv,
             const float* __restrict__ sc,
             const float* __restrict__ wLmv, const float* __restrict__ wLs,
             const float* __restrict__ wRmv, const float* __restrict__ wRs,
             const float* __restrict__ wJLmv, const float* __restrict__ wJLs,
             const float* __restrict__ wJRmv, const float* __restrict__ wJRs,
             const float* __restrict__ wOmv,  const float* __restrict__ wOs2mv,
             const float* __restrict__ wM2s,  const float* __restrict__ wS2s,
             float* __restrict__ out, int quadsTotal, int P)
{
    extern __shared__ float sm[];
    const int tid  = threadIdx.x;
    const int warp = tid >> 5;
    const int lane = tid & 31;

    // ---------------- weight repacks ----------------
    {
        const float* wsrc[4] = { wLmv, wRmv, wJLmv, wJRmv };
        for (int idx = tid; idx < 18432; idx += NTHR){
            int i = idx / 576, rem = idx % 576;
            int l, r, b;
            if (rem < 512){ int q = rem >> 7, rr = rem & 127; l = rr >> 2; int c = rr & 3; b = 2*q + (c>>1); r = c & 1; }
            else          { int rr = rem - 512; l = rr >> 1; r = rr & 1; b = 8; }
            int t = (l < 16) ? r : 2 + r;
            int o = l & 15;
            sm[OFF_WMV + idx] = wsrc[t][(o*32 + i)*9 + b];
        }
        const float* ssrc[4] = { wLs, wRs, wJLs, wJRs };
        for (int idx = tid; idx < 4096; idx += NTHR){
            int s2 = idx >> 7, rr = idx & 127, l = rr >> 2, c = rr & 3;
            int r = c & 1, se = c >> 1;
            int t = (l < 16) ? r : 2 + r;
            int o = l & 15;
            sm[OFF_WS + idx] = ssrc[t][o*64 + s2*2 + se];
        }
        for (int idx = tid; idx < 9216; idx += NTHR){
            int i = idx / 288, rem = idx % 288;
            int l, b;
            if (rem < 256){ int q = rem >> 7, rr = rem & 127; l = rr >> 2; b = 4*q + (rr & 3); }
            else          { l = rem - 256; b = 8; }
            sm[OFF_WOM + idx] = wOmv[(l*32 + i)*9 + b];
        }
        for (int idx = tid; idx < 2048; idx += NTHR){
            int c2 = idx >> 7, rr = idx & 127, l = rr >> 2, c4 = rr & 3;
            int r = c4 & 1, ce = c4 >> 1;
            sm[OFF_WM2S + idx] = wM2s[(l + 32*r)*32 + c2*2 + ce];
        }
        for (int idx = tid; idx < 4096; idx += NTHR){
            int s2 = idx >> 7, rr = idx & 127, l = rr >> 2, c4 = rr & 3;
            int r = c4 & 1, se = c4 >> 1;
            sm[OFF_WS2S + idx] = wS2s[(l + 32*r)*64 + s2*2 + se];
        }
    }
    __syncthreads();

    float* xs = sm + OFF_STG + warp * STGW;   // pack pk at +pk*1152; rows [32][36]
    float* outs = out + (size_t)P * 512;
    const int gwarps = gridDim.x * NWARP;
    constexpr GaTabs T = ga_make();

    for (int quad = blockIdx.x*NWARP + warp; quad < quadsTotal; quad += gwarps){
        const int p0 = quad * 4;
        const float2* sp0 = (const float2*)(sc + (size_t)(p0+0)*64);
        const float2* sp1 = (const float2*)(sc + (size_t)(p0+1)*64);
        const float2* sp2 = (const float2*)(sc + (size_t)(p0+2)*64);
        const float2* sp3 = (const float2*)(sc + (size_t)(p0+3)*64);

        __syncwarp();
        // stage x: rows [i][8 groups of 4 floats at immediate offsets]
        #pragma unroll
        for (int pk = 0; pk < 2; ++pk){
            const int pa = p0 + 2*pk;
            const float4* sA = (const float4*)(mv + (size_t)pa * 512);
            const float4* sB = sA + 128;
            float* xsp = xs + pk*1152;
            #pragma unroll
            for (int k = 0; k < 4; ++k){
                int q = lane + 32*k;
                float4 a = sA[q], b = sB[q];
                int i = q >> 2, gp = (q & 3) * 2;
                float* dst = xsp + i*36 + gp*4;
                *(ulonglong2*)(dst    ) = make_ulonglong2(pk2(a.x,b.x), pk2(a.y,b.y));
                *(ulonglong2*)(dst + 4) = make_ulonglong2(pk2(a.z,b.z), pk2(a.w,b.w));
            }
        }
        __syncwarp();

        // phase 1: 4 equi_linears for 4 positions
        u64 acc0[2][16], acc1[2][16];
        #pragma unroll
        for (int pk = 0; pk < 2; ++pk)
            #pragma unroll
            for (int j = 0; j < 16; ++j){ acc0[pk][j] = 0ull; acc1[pk][j] = 0ull; }

        #pragma unroll 1
        for (int i = 0; i < 32; ++i){
            const float* wp = sm + OFF_WMV + i*576;
            float4 f0 = ((const float4*)(wp      ))[lane];
            float4 f1 = ((const float4*)(wp + 128))[lane];
            float4 f2 = ((const float4*)(wp + 256))[lane];
            float4 f3 = ((const float4*)(wp + 384))[lane];
            float w8a, w8b; unpk2(((const u64*)(wp + 512))[lane], w8a, w8b);
            #pragma unroll
            for (int pk = 0; pk < 2; ++pk){
                u64 x2[16];
                const ulonglong2* xp = (const ulonglong2*)(xs + pk*1152 + i*36);
                #pragma unroll
                for (int p = 0; p < 8; ++p){ ulonglong2 v = xp[p]; x2[2*p] = v.x; x2[2*p+1] = v.y; }
                apply_b2<0>(f0.x, f0.y, x2, acc0[pk], acc1[pk]);
                apply_b2<1>(f0.z, f0.w, x2, acc0[pk], acc1[pk]);
                apply_b2<2>(f1.x, f1.y, x2, acc0[pk], acc1[pk]);
                apply_b2<3>(f1.z, f1.w, x2, acc0[pk], acc1[pk]);
                apply_b2<4>(f2.x, f2.y, x2, acc0[pk], acc1[pk]);
                apply_b2<5>(f2.z, f2.w, x2, acc0[pk], acc1[pk]);
                apply_b2<6>(f3.x, f3.y, x2, acc0[pk], acc1[pk]);
                apply_b2<7>(f3.z, f3.w, x2, acc0[pk], acc1[pk]);
                apply_b2<8>(w8a,  w8b,  x2, acc0[pk], acc1[pk]);
            }
        }

        // scalar contribution into component 0
        #pragma unroll 4
        for (int s2 = 0; s2 < 32; ++s2){
            float4 w = ((const float4*)(sm + OFF_WS + s2*128))[lane];
            float2 va = __ldg(sp0 + s2), vb = __ldg(sp1 + s2);
            float2 vc = __ldg(sp2 + s2), vd = __ldg(sp3 + s2);
            u64 e01 = pk2(va.x, vb.x), o01 = pk2(va.y, vb.y);
            u64 e23 = pk2(vc.x, vd.x), o23 = pk2(vc.y, vd.y);
            acc0[0][0] = fma2(dup2(w.x), e01, acc0[0][0]);
            acc1[0][0] = fma2(dup2(w.y), e01, acc1[0][0]);
            acc0[0][0] = fma2(dup2(w.z), o01, acc0[0][0]);
            acc1[0][0] = fma2(dup2(w.w), o01, acc1[0][0]);
            acc0[1][0] = fma2(dup2(w.x), e23, acc0[1][0]);
            acc1[1][0] = fma2(dup2(w.y), e23, acc1[1][0]);
            acc0[1][0] = fma2(dup2(w.z), o23, acc0[1][0]);
            acc1[1][0] = fma2(dup2(w.w), o23, acc1[1][0]);
        }

        // bilinears; store h back into staging
        #pragma unroll
        for (int pk = 0; pk < 2; ++pk){
            const int pa = p0 + 2*pk;
            u64 h2[16];
            #pragma unroll
            for (int j = 0; j < 16; ++j) h2[j] = 0ull;

            if (lane < 16){
                #pragma unroll
                for (int j = 0; j < 16; ++j)
                    #pragma unroll
                    for (int k = 0; k < 16; ++k)
                        if (T.gs[j][k] != 0){
                            u64 a = (T.gs[j][k] > 0) ? acc0[pk][j] : neg2(acc0[pk][j]);
                            h2[T.gi[j][k]] = fma2(a, acc1[pk][k], h2[T.gi[j][k]]);
                        }
            } else {
                u64 lam2 = pk2(__ldg(refmv + (size_t)pa*16 + 15), __ldg(refmv + (size_t)(pa+1)*16 + 15));
                #pragma unroll
                for (int j = 0; j < 16; ++j)
                    #pragma unroll
                    for (int k = 0; k < 16; ++k)
                        if (T.js[j][k] != 0){
                            u64 a = (T.js[j][k] > 0) ? acc0[pk][j] : neg2(acc0[pk][j]);
                            h2[T.ja[j][k]] = fma2(a, acc1[pk][k], h2[T.ja[j][k]]);
                        }
                #pragma unroll
                for (int j = 0; j < 16; ++j) h2[j] = mul2(h2[j], lam2);
            }
            ulonglong2* hr = (ulonglong2*)(xs + pk*1152 + lane*36);
            #pragma unroll
            for (int p = 0; p < 8; ++p) hr[p] = make_ulonglong2(h2[2*p], h2[2*p+1]);
        }
        __syncwarp();

        // phase 2: output equi_linear (o = lane)
        u64 ao[2][16];
        #pragma unroll
        for (int pk = 0; pk < 2; ++pk)
            #pragma unroll
            for (int j = 0; j < 16; ++j) ao[pk][j] = 0ull;

        #pragma unroll 1
        for (int i = 0; i < 32; ++i){
            const float* wp = sm + OFF_WOM + i*288;
            float4 g0 = ((const float4*)(wp      ))[lane];
            float4 g1 = ((const float4*)(wp + 128))[lane];
            float wb8 = wp[256 + lane];
            #pragma unroll
            for (int pk = 0; pk < 2; ++pk){
                u64 x2[16];
                const ulonglong2* xp = (const ulonglong2*)(xs + pk*1152 + i*36);
                #pragma unroll
                for (int p = 0; p < 8; ++p){ ulonglong2 v = xp[p]; x2[2*p] = v.x; x2[2*p+1] = v.y; }
                apply_b1<0>(g0.x, x2, ao[pk]);
                apply_b1<1>(g0.y, x2, ao[pk]);
                apply_b1<2>(g0.z, x2, ao[pk]);
                apply_b1<3>(g0.w, x2, ao[pk]);
                apply_b1<4>(g1.x, x2, ao[pk]);
                apply_b1<5>(g1.y, x2, ao[pk]);
                apply_b1<6>(g1.z, x2, ao[pk]);
                apply_b1<7>(g1.w, x2, ao[pk]);
                apply_b1<8>(wb8,  x2, ao[pk]);
            }
        }

        // scalars into component 0 (weights via uniform-ish LDG, 8KB L1-resident)
        {
            const u64* wsm = (const u64*)(wOs2mv + (size_t)lane*64);
            #pragma unroll 4
            for (int s2 = 0; s2 < 32; ++s2){
                float we, wo; unpk2(__ldg(wsm + s2), we, wo);
                float2 va = __ldg(sp0 + s2), vb = __ldg(sp1 + s2);
                float2 vc = __ldg(sp2 + s2), vd = __ldg(sp3 + s2);
                u64 dwe = dup2(we), dwo = dup2(wo);
                ao[0][0] = fma2(dwe, pk2(va.x, vb.x), ao[0][0]);
                ao[0][0] = fma2(dwo, pk2(va.y, vb.y), ao[0][0]);
                ao[1][0] = fma2(dwe, pk2(vc.x, vd.x), ao[1][0]);
                ao[1][0] = fma2(dwo, pk2(vc.y, vd.y), ao[1][0]);
            }
        }

        // store out_mv (4 positions)
        #pragma unroll
        for (int pk = 0; pk < 2; ++pk){
            const int pa = p0 + 2*pk;
            float v0[16], v1[16];
            #pragma unroll
            for (int j = 0; j < 16; ++j) unpk2(ao[pk][j], v0[j], v1[j]);
            float* op0 = out + ((size_t)pa*32 + lane)*16;
            float* op1 = op0 + 512;
            #pragma unroll
            for (int j = 0; j < 16; j += 4){
                *(float4*)(op0 + j) = make_float4(v0[j], v0[j+1], v0[j+2], v0[j+3]);
                *(float4*)(op1 + j) = make_float4(v1[j], v1[j+1], v1[j+2], v1[j+3]);
            }
        }

        // out_s: lane owns outputs (lane, lane+32)
        u64 as[2][2] = {{0ull,0ull},{0ull,0ull}};
        #pragma unroll
        for (int c2 = 0; c2 < 16; ++c2){
            float4 w = ((const float4*)(sm + OFF_WM2S + c2*128))[lane];
            u64 dwx = dup2(w.x), dwy = dup2(w.y), dwz = dup2(w.z), dww = dup2(w.w);
            const int re = 2*c2, ro = 2*c2 + 1;
            #pragma unroll
            for (int pk = 0; pk < 2; ++pk){
                u64 hev = *(const u64*)(xs + pk*1152 + re*36);
                u64 hod = *(const u64*)(xs + pk*1152 + ro*36);
                as[pk][0] = fma2(dwx, hev, as[pk][0]);
                as[pk][1] = fma2(dwy, hev, as[pk][1]);
                as[pk][0] = fma2(dwz, hod, as[pk][0]);
                as[pk][1] = fma2(dww, hod, as[pk][1]);
            }
        }
        #pragma unroll 4
        for (int s2 = 0; s2 < 32; ++s2){
            float4 w = ((const float4*)(sm + OFF_WS2S + s2*128))[lane];
            float2 va = __ldg(sp0 + s2), vb = __ldg(sp1 + s2);
            float2 vc = __ldg(sp2 + s2), vd = __ldg(sp3 + s2);
            u64 e01 = pk2(va.x, vb.x), o01 = pk2(va.y, vb.y);
            u64 e23 = pk2(vc.x, vd.x), o23 = pk2(vc.y, vd.y);
            as[0][0] = fma2(dup2(w.x), e01, as[0][0]);
            as[0][1] = fma2(dup2(w.y), e01, as[0][1]);
            as[0][0] = fma2(dup2(w.z), o01, as[0][0]);
            as[0][1] = fma2(dup2(w.w), o01, as[0][1]);
            as[1][0] = fma2(dup2(w.x), e23, as[1][0]);
            as[1][1] = fma2(dup2(w.y), e23, as[1][1]);
            as[1][0] = fma2(dup2(w.z), o23, as[1][0]);
            as[1][1] = fma2(dup2(w.w), o23, as[1][1]);
        }
        #pragma unroll
        for (int pk = 0; pk < 2; ++pk){
            const int pa = p0 + 2*pk;
            float a0, a1, b0, b1;
            unpk2(as[pk][0], a0, a1);
            unpk2(as[pk][1], b0, b1);
            outs[(size_t)pa*64 + lane]          = a0;
            outs[(size_t)(pa+1)*64 + lane]      = a1;
            outs[(size_t)pa*64 + 32 + lane]     = b0;
            outs[(size_t)(pa+1)*64 + 32 + lane] = b1;
        }
    }
}

// ---------------------------------------------------------------------------
// launch
// ---------------------------------------------------------------------------
extern "C" void kernel_launch(void* const* d_in, const int* in_sizes, int n_in,
                              void* d_out, int out_size)
{
    const float* mv    = (const float*)d_in[0];
    const float* refmv = (const float*)d_in[1];
    const float* sc    = (const float*)d_in[2];
    const float* wLmv  = (const float*)d_in[6];
    const float* wLs   = (const float*)d_in[7];
    const float* wRmv  = (const float*)d_in[8];
    const float* wRs   = (const float*)d_in[9];
    const float* wJLmv = (const float*)d_in[10];
    const float* wJLs  = (const float*)d_in[11];
    const float* wJRmv = (const float*)d_in[12];
    const float* wJRs  = (const float*)d_in[13];
    const float* wOmv  = (const float*)d_in[14];
    const float* wOs2m = (const float*)d_in[15];
    const float* wM2s  = (const float*)d_in[16];
    const float* wS2s  = (const float*)d_in[17];
    float* out = (float*)d_out;

    const int P = in_sizes[0] / (32 * 16);
    const int quads = P / 4;

    int sms = 148;
    cudaDeviceGetAttribute(&sms, cudaDevAttrMultiProcessorCount, 0);

    const size_t smem = (size_t)SMEMF * sizeof(float);
    cudaFuncSetAttribute(fused_kernel, cudaFuncAttributeMaxDynamicSharedMemorySize, (int)smem);

    fused_kernel<<<sms, NTHR, smem>>>(mv, refmv, sc,
                                      wLmv, wLs, wRmv, wRs,
                                      wJLmv, wJLs, wJRmv, wJRs,
                                      wOmv, wOs2m, wM2s, wS2s,
                                      out, quads, P);
}

// round 7
// speedup vs baseline: 1.0029x; 1.0029x over previous
#include <cuda_runtime.h>

#define NWARP 8
#define NTHR  (NWARP*32)

// ---------------------------------------------------------------------------
// Compile-time geometric algebra for Cl(3,0,1), METRIC=(0,1,1,1).
// ---------------------------------------------------------------------------
__host__ __device__ constexpr int ga_popc(int x){ return (x&1)+((x>>1)&1)+((x>>2)&1)+((x>>3)&1); }
__host__ __device__ constexpr int ga_mask(int i){
    return i==0?0: i==1?1: i==2?2: i==3?4: i==4?8: i==5?3: i==6?5: i==7?9:
           i==8?6: i==9?10: i==10?12: i==11?7: i==12?11: i==13?13: i==14?14: 15;
}
__host__ __device__ constexpr int ga_idx(int m){
    return m==0?0: m==1?1: m==2?2: m==4?3: m==8?4: m==3?5: m==5?6: m==9?7:
           m==6?8: m==10?9: m==12?10: m==7?11: m==11?12: m==13?13: m==14?14: 15;
}
__host__ __device__ constexpr int ga_grade(int i){ return ga_popc(ga_mask(i)); }
__host__ __device__ constexpr int ga_csign(int a, int b){
    int s = 0;
    for (int i = 0; i < 4; ++i) if ((b>>i)&1) s += ga_popc(a >> (i+1));
    return (s&1) ? -1 : 1;
}
__host__ __device__ constexpr int ga_dsign(int b){ return ga_csign(ga_mask(b), 15 ^ ga_mask(b)); }

struct GaTabs {
    signed char gs[16][16]; signed char gi[16][16];
    signed char js[16][16]; signed char ja[16][16];
};
__host__ __device__ constexpr GaTabs ga_make(){
    GaTabs t{};
    for (int j = 0; j < 16; ++j)
        for (int k = 0; k < 16; ++k){
            int mj = ga_mask(j), mk = ga_mask(k);
            if (mj & mk & 1){ t.gs[j][k] = 0; t.gi[j][k] = 0; }
            else { t.gs[j][k] = (signed char)ga_csign(mj, mk); t.gi[j][k] = (signed char)ga_idx(mj ^ mk); }
            int jm = 15 ^ mj, km = 15 ^ mk;
            if (jm & km){ t.js[j][k] = 0; t.ja[j][k] = 0; }
            else {
                int im = jm ^ km;
                int s = ga_csign(im, 15 ^ im) * ga_csign(jm, km) * ga_dsign(j) * ga_dsign(k);
                t.js[j][k] = (signed char)s;
                t.ja[j][k] = (signed char)ga_idx(15 ^ im);
            }
        }
    return t;
}

// ---------------------------------------------------------------------------
// packed f32x2 helpers
// ---------------------------------------------------------------------------
typedef unsigned long long u64;
__device__ __forceinline__ u64 pk2(float a, float b){ u64 r; asm("mov.b64 %0,{%1,%2};":"=l"(r):"f"(a),"f"(b)); return r; }
__device__ __forceinline__ void unpk2(u64 v, float& a, float& b){ asm("mov.b64 {%0,%1},%2;":"=f"(a),"=f"(b):"l"(v)); }
__device__ __forceinline__ u64 dup2(float a){ u64 r; asm("mov.b64 %0,{%1,%1};":"=l"(r):"f"(a)); return r; }
__device__ __forceinline__ u64 fma2(u64 a, u64 b, u64 c){ u64 d; asm("fma.rn.f32x2 %0,%1,%2,%3;":"=l"(d):"l"(a),"l"(b),"l"(c)); return d; }
__device__ __forceinline__ u64 mul2(u64 a, u64 b){ u64 d; asm("mul.rn.f32x2 %0,%1,%2;":"=l"(d):"l"(a),"l"(b)); return d; }
__device__ __forceinline__ u64 neg2(u64 a){ return a ^ 0x8000000080000000ull; }

// apply basis map B to packed accumulators (compile-time B)
template<int B>
__device__ __forceinline__ void apply_b2(float wa, float wb, const u64* x2, u64* a0, u64* a1){
    u64 w0 = dup2(wa), w1 = dup2(wb);
    #pragma unroll
    for (int j = 0; j < 16; ++j){
        if (B < 5){
            if (ga_grade(j) == B){ a0[j] = fma2(w0, x2[j], a0[j]); a1[j] = fma2(w1, x2[j], a1[j]); }
        } else {
            if (!(ga_mask(j)&1) && ga_grade(j) == B-5){
                const int jj = ga_idx(ga_mask(j)|1);
                a0[jj] = fma2(w0, x2[j], a0[jj]); a1[jj] = fma2(w1, x2[j], a1[jj]);
            }
        }
    }
}
template<int B>
__device__ __forceinline__ void apply_b1(float wv, const u64* x2, u64* a){
    u64 w = dup2(wv);
    #pragma unroll
    for (int j = 0; j < 16; ++j){
        if (B < 5){
            if (ga_grade(j) == B) a[j] = fma2(w, x2[j], a[j]);
        } else {
            if (!(ga_mask(j)&1) && ga_grade(j) == B-5){
                const int jj = ga_idx(ga_mask(j)|1);
                a[jj] = fma2(w, x2[j], a[jj]);
            }
        }
    }
}

// ---------------------------------------------------------------------------
// smem layout (floats). Staging: per warp 2 packs x 32 rows x 36 floats.
// ---------------------------------------------------------------------------
#define OFF_WMV   0
#define OFF_WS    (OFF_WMV + 18432)
#define OFF_WOM   (OFF_WS  + 4096)
#define OFF_WM2S  (OFF_WOM + 9216)
#define OFF_WS2S  (OFF_WM2S+ 2048)
#define OFF_STG   (OFF_WS2S+ 4096)
#define STGW      2304
#define SMEMF (OFF_STG + NWARP*STGW)   /* 56320 floats = 225.3 KB */

__global__ void __launch_bounds__(NTHR, 1)
fused_kernel(const float* __restrict__ mv, const float* __restrict__ refmv,
             const float* __restrict__ sc,
             const float* __restrict__ wLmv, const float* __restrict__ wLs,
             const float* __restrict__ wRmv, const float* __restrict__ wRs,
             const float* __restrict__ wJLmv, const float* __restrict__ wJLs,
             const float* __restrict__ wJRmv, const float* __restrict__ wJRs,
             const float* __restrict__ wOmv,  const float* __restrict__ wOs2mv,
             const float* __restrict__ wM2s,  const float* __restrict__ wS2s,
             float* __restrict__ out, int quadsTotal, int P)
{
    extern __shared__ float sm[];
    const int tid  = threadIdx.x;
    const int warp = tid >> 5;
    const int lane = tid & 31;

    // ---------------- weight repacks ----------------
    {
        const float* wsrc[4] = { wLmv, wRmv, wJLmv, wJRmv };
        for (int idx = tid; idx < 18432; idx += NTHR){
            int i = idx / 576, rem = idx % 576;
            int l, r, b;
            if (rem < 512){ int q = rem >> 7, rr = rem & 127; l = rr >> 2; int c = rr & 3; b = 2*q + (c>>1); r = c & 1; }
            else          { int rr = rem - 512; l = rr >> 1; r = rr & 1; b = 8; }
            int t = (l < 16) ? r : 2 + r;
            int o = l & 15;
            sm[OFF_WMV + idx] = wsrc[t][(o*32 + i)*9 + b];
        }
        const float* ssrc[4] = { wLs, wRs, wJLs, wJRs };
        for (int idx = tid; idx < 4096; idx += NTHR){
            int s2 = idx >> 7, rr = idx & 127, l = rr >> 2, c = rr & 3;
            int r = c & 1, se = c >> 1;
            int t = (l < 16) ? r : 2 + r;
            int o = l & 15;
            sm[OFF_WS + idx] = ssrc[t][o*64 + s2*2 + se];
        }
        for (int idx = tid; idx < 9216; idx += NTHR){
            int i = idx / 288, rem = idx % 288;
            int l, b;
            if (rem < 256){ int q = rem >> 7, rr = rem & 127; l = rr >> 2; b = 4*q + (rr & 3); }
            else          { l = rem - 256; b = 8; }
            sm[OFF_WOM + idx] = wOmv[(l*32 + i)*9 + b];
        }
        for (int idx = tid; idx < 2048; idx += NTHR){
            int c2 = idx >> 7, rr = idx & 127, l = rr >> 2, c4 = rr & 3;
            int r = c4 & 1, ce = c4 >> 1;
            sm[OFF_WM2S + idx] = wM2s[(l + 32*r)*32 + c2*2 + ce];
        }
        for (int idx = tid; idx < 4096; idx += NTHR){
            int s2 = idx >> 7, rr = idx & 127, l = rr >> 2, c4 = rr & 3;
            int r = c4 & 1, se = c4 >> 1;
            sm[OFF_WS2S + idx] = wS2s[(l + 32*r)*64 + s2*2 + se];
        }
    }
    __syncthreads();

    float* xs = sm + OFF_STG + warp * STGW;   // pack pk at +pk*1152; rows [32][36]
    float* outs = out + (size_t)P * 512;
    const int gwarps = gridDim.x * NWARP;
    constexpr GaTabs T = ga_make();

    for (int quad = blockIdx.x*NWARP + warp; quad < quadsTotal; quad += gwarps){
        const int p0 = quad * 4;
        const float2* sp0 = (const float2*)(sc + (size_t)(p0+0)*64);
        const float2* sp1 = (const float2*)(sc + (size_t)(p0+1)*64);
        const float2* sp2 = (const float2*)(sc + (size_t)(p0+2)*64);
        const float2* sp3 = (const float2*)(sc + (size_t)(p0+3)*64);

        __syncwarp();
        // stage x: rows [i][8 groups of 4 floats at immediate offsets]
        #pragma unroll
        for (int pk = 0; pk < 2; ++pk){
            const int pa = p0 + 2*pk;
            const float4* sA = (const float4*)(mv + (size_t)pa * 512);
            const float4* sB = sA + 128;
            float* xsp = xs + pk*1152;
            #pragma unroll
            for (int k = 0; k < 4; ++k){
                int q = lane + 32*k;
                float4 a = sA[q], b = sB[q];
                int i = q >> 2, gp = (q & 3) * 2;
                float* dst = xsp + i*36 + gp*4;
                *(ulonglong2*)(dst    ) = make_ulonglong2(pk2(a.x,b.x), pk2(a.y,b.y));
                *(ulonglong2*)(dst + 4) = make_ulonglong2(pk2(a.z,b.z), pk2(a.w,b.w));
            }
        }
        __syncwarp();

        // phase 1: 4 equi_linears for 4 positions
        u64 acc0[2][16], acc1[2][16];
        #pragma unroll
        for (int pk = 0; pk < 2; ++pk)
            #pragma unroll
            for (int j = 0; j < 16; ++j){ acc0[pk][j] = 0ull; acc1[pk][j] = 0ull; }

        #pragma unroll 1
        for (int i = 0; i < 32; ++i){
            const float* wp = sm + OFF_WMV + i*576;
            float4 f0 = ((const float4*)(wp      ))[lane];
            float4 f1 = ((const float4*)(wp + 128))[lane];
            float4 f2 = ((const float4*)(wp + 256))[lane];
            float4 f3 = ((const float4*)(wp + 384))[lane];
            float w8a, w8b; unpk2(((const u64*)(wp + 512))[lane], w8a, w8b);
            #pragma unroll
            for (int pk = 0; pk < 2; ++pk){
                u64 x2[16];
                const ulonglong2* xp = (const ulonglong2*)(xs + pk*1152 + i*36);
                #pragma unroll
                for (int p = 0; p < 8; ++p){ ulonglong2 v = xp[p]; x2[2*p] = v.x; x2[2*p+1] = v.y; }
                apply_b2<0>(f0.x, f0.y, x2, acc0[pk], acc1[pk]);
                apply_b2<1>(f0.z, f0.w, x2, acc0[pk], acc1[pk]);
                apply_b2<2>(f1.x, f1.y, x2, acc0[pk], acc1[pk]);
                apply_b2<3>(f1.z, f1.w, x2, acc0[pk], acc1[pk]);
                apply_b2<4>(f2.x, f2.y, x2, acc0[pk], acc1[pk]);
                apply_b2<5>(f2.z, f2.w, x2, acc0[pk], acc1[pk]);
                apply_b2<6>(f3.x, f3.y, x2, acc0[pk], acc1[pk]);
                apply_b2<7>(f3.z, f3.w, x2, acc0[pk], acc1[pk]);
                apply_b2<8>(w8a,  w8b,  x2, acc0[pk], acc1[pk]);
            }
        }

        // scalar contribution into component 0
        #pragma unroll 4
        for (int s2 = 0; s2 < 32; ++s2){
            float4 w = ((const float4*)(sm + OFF_WS + s2*128))[lane];
            float2 va = __ldg(sp0 + s2), vb = __ldg(sp1 + s2);
            float2 vc = __ldg(sp2 + s2), vd = __ldg(sp3 + s2);
            u64 e01 = pk2(va.x, vb.x), o01 = pk2(va.y, vb.y);
            u64 e23 = pk2(vc.x, vd.x), o23 = pk2(vc.y, vd.y);
            acc0[0][0] = fma2(dup2(w.x), e01, acc0[0][0]);
            acc1[0][0] = fma2(dup2(w.y), e01, acc1[0][0]);
            acc0[0][0] = fma2(dup2(w.z), o01, acc0[0][0]);
            acc1[0][0] = fma2(dup2(w.w), o01, acc1[0][0]);
            acc0[1][0] = fma2(dup2(w.x), e23, acc0[1][0]);
            acc1[1][0] = fma2(dup2(w.y), e23, acc1[1][0]);
            acc0[1][0] = fma2(dup2(w.z), o23, acc0[1][0]);
            acc1[1][0] = fma2(dup2(w.w), o23, acc1[1][0]);
        }

        // bilinears; store h back into staging
        #pragma unroll
        for (int pk = 0; pk < 2; ++pk){
            const int pa = p0 + 2*pk;
            u64 h2[16];
            #pragma unroll
            for (int j = 0; j < 16; ++j) h2[j] = 0ull;

            if (lane < 16){
                #pragma unroll
                for (int j = 0; j < 16; ++j)
                    #pragma unroll
                    for (int k = 0; k < 16; ++k)
                        if (T.gs[j][k] != 0){
                            u64 a = (T.gs[j][k] > 0) ? acc0[pk][j] : neg2(acc0[pk][j]);
                            h2[T.gi[j][k]] = fma2(a, acc1[pk][k], h2[T.gi[j][k]]);
                        }
            } else {
                u64 lam2 = pk2(__ldg(refmv + (size_t)pa*16 + 15), __ldg(refmv + (size_t)(pa+1)*16 + 15));
                #pragma unroll
                for (int j = 0; j < 16; ++j)
                    #pragma unroll
                    for (int k = 0; k < 16; ++k)
                        if (T.js[j][k] != 0){
                            u64 a = (T.js[j][k] > 0) ? acc0[pk][j] : neg2(acc0[pk][j]);
                            h2[T.ja[j][k]] = fma2(a, acc1[pk][k], h2[T.ja[j][k]]);
                        }
                #pragma unroll
                for (int j = 0; j < 16; ++j) h2[j] = mul2(h2[j], lam2);
            }
            ulonglong2* hr = (ulonglong2*)(xs + pk*1152 + lane*36);
            #pragma unroll
            for (int p = 0; p < 8; ++p) hr[p] = make_ulonglong2(h2[2*p], h2[2*p+1]);
        }
        __syncwarp();

        // phase 2: output equi_linear (o = lane)
        u64 ao[2][16];
        #pragma unroll
        for (int pk = 0; pk < 2; ++pk)
            #pragma unroll
            for (int j = 0; j < 16; ++j) ao[pk][j] = 0ull;

        #pragma unroll 1
        for (int i = 0; i < 32; ++i){
            const float* wp = sm + OFF_WOM + i*288;
            float4 g0 = ((const float4*)(wp      ))[lane];
            float4 g1 = ((const float4*)(wp + 128))[lane];
            float wb8 = wp[256 + lane];
            #pragma unroll
            for (int pk = 0; pk < 2; ++pk){
                u64 x2[16];
                const ulonglong2* xp = (const ulonglong2*)(xs + pk*1152 + i*36);
                #pragma unroll
                for (int p = 0; p < 8; ++p){ ulonglong2 v = xp[p]; x2[2*p] = v.x; x2[2*p+1] = v.y; }
                apply_b1<0>(g0.x, x2, ao[pk]);
                apply_b1<1>(g0.y, x2, ao[pk]);
                apply_b1<2>(g0.z, x2, ao[pk]);
                apply_b1<3>(g0.w, x2, ao[pk]);
                apply_b1<4>(g1.x, x2, ao[pk]);
                apply_b1<5>(g1.y, x2, ao[pk]);
                apply_b1<6>(g1.z, x2, ao[pk]);
                apply_b1<7>(g1.w, x2, ao[pk]);
                apply_b1<8>(wb8,  x2, ao[pk]);
            }
        }

        // scalars into component 0 (weights via uniform-ish LDG, 8KB L1-resident)
        {
            const u64* wsm = (const u64*)(wOs2mv + (size_t)lane*64);
            #pragma unroll 4
            for (int s2 = 0; s2 < 32; ++s2){
                float we, wo; unpk2(__ldg(wsm + s2), we, wo);
                float2 va = __ldg(sp0 + s2), vb = __ldg(sp1 + s2);
                float2 vc = __ldg(sp2 + s2), vd = __ldg(sp3 + s2);
                u64 dwe = dup2(we), dwo = dup2(wo);
                ao[0][0] = fma2(dwe, pk2(va.x, vb.x), ao[0][0]);
                ao[0][0] = fma2(dwo, pk2(va.y, vb.y), ao[0][0]);
                ao[1][0] = fma2(dwe, pk2(vc.x, vd.x), ao[1][0]);
                ao[1][0] = fma2(dwo, pk2(vc.y, vd.y), ao[1][0]);
            }
        }

        // store out_mv (4 positions)
        #pragma unroll
        for (int pk = 0; pk < 2; ++pk){
            const int pa = p0 + 2*pk;
            float v0[16], v1[16];
            #pragma unroll
            for (int j = 0; j < 16; ++j) unpk2(ao[pk][j], v0[j], v1[j]);
            float* op0 = out + ((size_t)pa*32 + lane)*16;
            float* op1 = op0 + 512;
            #pragma unroll
            for (int j = 0; j < 16; j += 4){
                *(float4*)(op0 + j) = make_float4(v0[j], v0[j+1], v0[j+2], v0[j+3]);
                *(float4*)(op1 + j) = make_float4(v1[j], v1[j+1], v1[j+2], v1[j+3]);
            }
        }

        // out_s: lane owns outputs (lane, lane+32)
        u64 as[2][2] = {{0ull,0ull},{0ull,0ull}};
        #pragma unroll
        for (int c2 = 0; c2 < 16; ++c2){
            float4 w = ((const float4*)(sm + OFF_WM2S + c2*128))[lane];
            u64 dwx = dup2(w.x), dwy = dup2(w.y), dwz = dup2(w.z), dww = dup2(w.w);
            const int re = 2*c2, ro = 2*c2 + 1;
            #pragma unroll
            for (int pk = 0; pk < 2; ++pk){
                u64 hev = *(const u64*)(xs + pk*1152 + re*36);
                u64 hod = *(const u64*)(xs + pk*1152 + ro*36);
                as[pk][0] = fma2(dwx, hev, as[pk][0]);
                as[pk][1] = fma2(dwy, hev, as[pk][1]);
                as[pk][0] = fma2(dwz, hod, as[pk][0]);
                as[pk][1] = fma2(dww, hod, as[pk][1]);
            }
        }
        #pragma unroll 4
        for (int s2 = 0; s2 < 32; ++s2){
            float4 w = ((const float4*)(sm + OFF_WS2S + s2*128))[lane];
            float2 va = __ldg(sp0 + s2), vb = __ldg(sp1 + s2);
            float2 vc = __ldg(sp2 + s2), vd = __ldg(sp3 + s2);
            u64 e01 = pk2(va.x, vb.x), o01 = pk2(va.y, vb.y);
            u64 e23 = pk2(vc.x, vd.x), o23 = pk2(vc.y, vd.y);
            as[0][0] = fma2(dup2(w.x), e01, as[0][0]);
            as[0][1] = fma2(dup2(w.y), e01, as[0][1]);
            as[0][0] = fma2(dup2(w.z), o01, as[0][0]);
            as[0][1] = fma2(dup2(w.w), o01, as[0][1]);
            as[1][0] = fma2(dup2(w.x), e23, as[1][0]);
            as[1][1] = fma2(dup2(w.y), e23, as[1][1]);
            as[1][0] = fma2(dup2(w.z), o23, as[1][0]);
            as[1][1] = fma2(dup2(w.w), o23, as[1][1]);
        }
        #pragma unroll
        for (int pk = 0; pk < 2; ++pk){
            const int pa = p0 + 2*pk;
            float a0, a1, b0, b1;
            unpk2(as[pk][0], a0, a1);
            unpk2(as[pk][1], b0, b1);
            outs[(size_t)pa*64 + lane]          = a0;
            outs[(size_t)(pa+1)*64 + lane]      = a1;
            outs[(size_t)pa*64 + 32 + lane]     = b0;
            outs[(size_t)(pa+1)*64 + 32 + lane] = b1;
        }
    }
}

// ---------------------------------------------------------------------------
// launch
// ---------------------------------------------------------------------------
extern "C" void kernel_launch(void* const* d_in, const int* in_sizes, int n_in,
                              void* d_out, int out_size)
{
    const float* mv    = (const float*)d_in[0];
    const float* refmv = (const float*)d_in[1];
    const float* sc    = (const float*)d_in[2];
    const float* wLmv  = (const float*)d_in[6];
    const float* wLs   = (const float*)d_in[7];
    const float* wRmv  = (const float*)d_in[8];
    const float* wRs   = (const float*)d_in[9];
    const float* wJLmv = (const float*)d_in[10];
    const float* wJLs  = (const float*)d_in[11];
    const float* wJRmv = (const float*)d_in[12];
    const float* wJRs  = (const float*)d_in[13];
    const float* wOmv  = (const float*)d_in[14];
    const float* wOs2m = (const float*)d_in[15];
    const float* wM2s  = (const float*)d_in[16];
    const float* wS2s  = (const float*)d_in[17];
    float* out = (float*)d_out;

    const int P = in_sizes[0] / (32 * 16);
    const int quads = P / 4;

    int sms = 148;
    cudaDeviceGetAttribute(&sms, cudaDevAttrMultiProcessorCount, 0);

    const size_t smem = (size_t)SMEMF * sizeof(float);
    cudaFuncSetAttribute(fused_kernel, cudaFuncAttributeMaxDynamicSharedMemorySize, (int)smem);

    fused_kernel<<<sms, NTHR, smem>>>(mv, refmv, sc,
                                      wLmv, wLs, wRmv, wRs,
                                      wJLmv, wJLs, wJRmv, wJRs,
                                      wOmv, wOs2m, wM2s, wS2s,
                                      out, quads, P);
}

// round 8
// speedup vs baseline: 1.1064x; 1.1033x over previous
#include <cuda_runtime.h>
#define NWARP 12
#define NTHR  (NWARP*32)
typedef unsigned long long u64;

__host__ __device__ constexpr int ga_popc(int x){ return (x&1)+((x>>1)&1)+((x>>2)&1)+((x>>3)&1); }
__host__ __device__ constexpr int ga_mask(int i){
    return i==0?0: i==1?1: i==2?2: i==3?4: i==4?8: i==5?3: i==6?5: i==7?9:
           i==8?6: i==9?10: i==10?12: i==11?7: i==12?11: i==13?13: i==14?14: 15;
}
__host__ __device__ constexpr int ga_idx(int m){
    return m==0?0: m==1?1: m==2?2: m==4?3: m==8?4: m==3?5: m==5?6: m==9?7:
           m==6?8: m==10?9: m==12?10: m==7?11: m==11?12: m==13?13: m==14?14: 15;
}
__host__ __device__ constexpr int ga_grade(int i){ return ga_popc(ga_mask(i)); }
__host__ __device__ constexpr int ga_csign(int a, int b){
    int s = 0;
    for (int i = 0; i < 4; ++i) if ((b>>i)&1) s += ga_popc(a >> (i+1));
    return (s&1) ? -1 : 1;
}
__host__ __device__ constexpr int ga_dsign(int b){ return ga_csign(ga_mask(b), 15 ^ ga_mask(b)); }

struct GaTabs { signed char gs[16][16], gi[16][16], js[16][16], ja[16][16]; };
__host__ __device__ constexpr GaTabs ga_make(){
    GaTabs t{};
    for (int j = 0; j < 16; ++j)
        for (int k = 0; k < 16; ++k){
            int mj = ga_mask(j), mk = ga_mask(k);
            if (mj & mk & 1){ t.gs[j][k]=0; t.gi[j][k]=0; }
            else { t.gs[j][k]=(signed char)ga_csign(mj,mk); t.gi[j][k]=(signed char)ga_idx(mj^mk); }
            int jm = 15^mj, km = 15^mk;
            if (jm & km){ t.js[j][k]=0; t.ja[j][k]=0; }
            else {
                int im = jm^km;
                int s = ga_csign(im,15^im)*ga_csign(jm,km)*ga_dsign(j)*ga_dsign(k);
                t.js[j][k]=(signed char)s; t.ja[j][k]=(signed char)ga_idx(15^im);
            }
        }
    return t;
}

__device__ __forceinline__ u64 pk2(float a, float b){ u64 r; asm("mov.b64 %0,{%1,%2};":"=l"(r):"f"(a),"f"(b)); return r; }
__device__ __forceinline__ void unpk2(u64 v, float& a, float& b){ asm("mov.b64 {%0,%1},%2;":"=f"(a),"=f"(b):"l"(v)); }
__device__ __forceinline__ u64 dup2(float a){ u64 r; asm("mov.b64 %0,{%1,%1};":"=l"(r):"f"(a)); return r; }
__device__ __forceinline__ u64 fma2(u64 a, u64 b, u64 c){ u64 d; asm("fma.rn.f32x2 %0,%1,%2,%3;":"=l"(d):"l"(a),"l"(b),"l"(c)); return d; }
__device__ __forceinline__ u64 mul2(u64 a, u64 b){ u64 d; asm("mul.rn.f32x2 %0,%1,%2;":"=l"(d):"l"(a),"l"(b)); return d; }
__device__ __forceinline__ u64 neg2(u64 a){ return a ^ 0x8000000080000000ull; }

template<int B>
__device__ __forceinline__ void apply_b2(float wa, float wb, const u64* x2, u64* a0, u64* a1){
    u64 w0 = dup2(wa), w1 = dup2(wb);
    #pragma unroll
    for (int j = 0; j < 16; ++j){
        if (B < 5){
            if (ga_grade(j) == B){ a0[j]=fma2(w0,x2[j],a0[j]); a1[j]=fma2(w1,x2[j],a1[j]); }
        } else {
            if (!(ga_mask(j)&1) && ga_grade(j) == B-5){
                const int jj = ga_idx(ga_mask(j)|1);
                a0[jj]=fma2(w0,x2[j],a0[jj]); a1[jj]=fma2(w1,x2[j],a1[jj]);
            }
        }
    }
}

static __device__ float g_ws[4096];
static __device__ float g_ws2m[2048];
static __device__ float g_wm2s[2048];
static __device__ float g_ws2s[4096];

__global__ void repack_kernel(const float* __restrict__ wLs, const float* __restrict__ wRs,
                              const float* __restrict__ wJLs, const float* __restrict__ wJRs,
                              const float* __restrict__ wOs2mv,
                              const float* __restrict__ wM2s, const float* __restrict__ wS2s)
{
    int tid = blockIdx.x*blockDim.x + threadIdx.x, nt = gridDim.x*blockDim.x;
    for (int idx = tid; idx < 4096; idx += nt){
        int c = idx&3, o = (idx>>2)&15, s2 = (idx>>6)&31, pass = idx>>11;
        int t = c&1, se = c>>1;
        const float* src = pass ? (t?wJRs:wJLs) : (t?wRs:wLs);
        g_ws[idx] = src[o*64 + 2*s2 + se];
    }
    for (int idx = tid; idx < 2048; idx += nt){
        int c = idx&3, o = (idx>>2)&15, s2 = idx>>6;
        g_ws2m[idx] = wOs2mv[(o + 16*(c&1))*64 + 2*s2 + (c>>1)];
    }
    for (int idx = tid; idx < 2048; idx += nt){
        int c4 = idx&3, l = (idx>>2)&31, c2 = idx>>7;
        g_wm2s[idx] = wM2s[(l + 32*(c4&1))*32 + c2*2 + (c4>>1)];
    }
    for (int idx = tid; idx < 4096; idx += nt){
        int c4 = idx&3, l = (idx>>2)&31, s2 = idx>>7;
        g_ws2s[idx] = wS2s[(l + 32*(c4&1))*64 + s2*2 + (c4>>1)];
    }
}

#define OFF_WMV 0
#define OFF_WOM 18432
#define OFF_STG 27648
#define PSTRIDE 1156
#define WSTG    (2*PSTRIDE)
#define SMEMF   (OFF_STG + NWARP*WSTG)

__device__ __forceinline__ void run_pass(const float* sm, const float* xph, const float* sc4,
                                         int o, int pass, u64* a0, u64* a1)
{
    #pragma unroll
    for (int j = 0; j < 16; ++j){ a0[j]=0ull; a1[j]=0ull; }
    const u64* wt = (const u64*)(sm + OFF_WMV) + (size_t)pass*4608;
    #pragma unroll 1
    for (int i = 0; i < 32; ++i){
        const u64* wi = wt + i*144;
        u64 x2[16];
        const ulonglong2* xp = (const ulonglong2*)(xph + i*36);
        #pragma unroll
        for (int t = 0; t < 8; ++t){ ulonglong2 v = xp[t]; x2[2*t]=v.x; x2[2*t+1]=v.y; }
        float wa, wb;
        unpk2(wi[0*16+o],wa,wb); apply_b2<0>(wa,wb,x2,a0,a1);
        unpk2(wi[1*16+o],wa,wb); apply_b2<1>(wa,wb,x2,a0,a1);
        unpk2(wi[2*16+o],wa,wb); apply_b2<2>(wa,wb,x2,a0,a1);
        unpk2(wi[3*16+o],wa,wb); apply_b2<3>(wa,wb,x2,a0,a1);
        unpk2(wi[4*16+o],wa,wb); apply_b2<4>(wa,wb,x2,a0,a1);
        unpk2(wi[5*16+o],wa,wb); apply_b2<5>(wa,wb,x2,a0,a1);
        unpk2(wi[6*16+o],wa,wb); apply_b2<6>(wa,wb,x2,a0,a1);
        unpk2(wi[7*16+o],wa,wb); apply_b2<7>(wa,wb,x2,a0,a1);
        unpk2(wi[8*16+o],wa,wb); apply_b2<8>(wa,wb,x2,a0,a1);
    }
    #pragma unroll 4
    for (int s2 = 0; s2 < 32; ++s2){
        float4 w = __ldg((const float4*)(g_ws + ((pass*32 + s2)*16 + o)*4));
        float2 va = __ldg((const float2*)sc4 + s2);
        float2 vb = __ldg((const float2*)(sc4 + 64) + s2);
        u64 sva = pk2(va.x, vb.x), svb = pk2(va.y, vb.y);
        a0[0]=fma2(dup2(w.x),sva,a0[0]); a1[0]=fma2(dup2(w.y),sva,a1[0]);
        a0[0]=fma2(dup2(w.z),svb,a0[0]); a1[0]=fma2(dup2(w.w),svb,a1[0]);
    }
}

__global__ void __launch_bounds__(NTHR, 1)
fused_kernel(const float* __restrict__ mv, const float* __restrict__ refmv,
             const float* __restrict__ sc,
             const float* __restrict__ wLmv, const float* __restrict__ wRmv,
             const float* __restrict__ wJLmv, const float* __restrict__ wJRmv,
             const float* __restrict__ wOmv,
             float* __restrict__ out, int quadsTotal, int P)
{
    extern __shared__ float sm[];
    const int tid = threadIdx.x, warp = tid>>5, lane = tid&31;
    const int ph = lane>>4, o = lane&15;

    for (int idx = tid; idx < 18432; idx += NTHR){
        int half = idx&1, oo = (idx>>1)&15, flat = idx>>5;
        int b = flat%9, r2 = flat/9, i = r2&31, pass = r2>>5;
        const float* src = pass ? (half?wJRmv:wJLmv) : (half?wRmv:wLmv);
        sm[OFF_WMV + idx] = src[(oo*32+i)*9 + b];
    }
    for (int idx = tid; idx < 9216; idx += NTHR){
        int half = idx&1, oo = (idx>>1)&15, flat = idx>>5;
        int b = flat%9, i = flat/9;
        sm[OFF_WOM + idx] = wOmv[((oo+16*half)*32+i)*9 + b];
    }
    __syncthreads();

    float* xs  = sm + OFF_STG + warp*WSTG;
    float* xph = xs + ph*PSTRIDE;
    float* outs = out + (size_t)P*512;
    const int gwarps = gridDim.x*NWARP;
    constexpr GaTabs T = ga_make();

    for (int quad = blockIdx.x*NWARP + warp; quad < quadsTotal; quad += gwarps){
        const int p0 = quad*4, pa = p0 + 2*ph;
        const float* sc4 = sc + (size_t)pa*64;

        __syncwarp();
        #pragma unroll
        for (int pk = 0; pk < 2; ++pk){
            const float4* sA = (const float4*)(mv + (size_t)(p0+2*pk)*512);
            const float4* sB = sA + 128;
            float* xsp = xs + pk*PSTRIDE;
            #pragma unroll
            for (int k = 0; k < 4; ++k){
                int q = lane + 32*k;
                float4 a = sA[q], b = sB[q];
                int i = q>>2, gp = (q&3)*2;
                float* dst = xsp + i*36 + gp*4;
                *(ulonglong2*)(dst  ) = make_ulonglong2(pk2(a.x,b.x), pk2(a.y,b.y));
                *(ulonglong2*)(dst+4) = make_ulonglong2(pk2(a.z,b.z), pk2(a.w,b.w));
            }
        }
        __syncwarp();

        u64 a0[16], a1[16], hg[16];
        run_pass(sm, xph, sc4, o, 0, a0, a1);
        #pragma unroll
        for (int j = 0; j < 16; ++j) hg[j] = 0ull;
        #pragma unroll
        for (int j = 0; j < 16; ++j)
            #pragma unroll
            for (int k = 0; k < 16; ++k)
                if (T.gs[j][k] != 0){
                    u64 a = (T.gs[j][k] > 0) ? a0[j] : neg2(a0[j]);
                    hg[T.gi[j][k]] = fma2(a, a1[k], hg[T.gi[j][k]]);
                }

        run_pass(sm, xph, sc4, o, 1, a0, a1);
        {
            u64 hj[16];
            #pragma unroll
            for (int j = 0; j < 16; ++j) hj[j] = 0ull;
            #pragma unroll
            for (int j = 0; j < 16; ++j)
                #pragma unroll
                for (int k = 0; k < 16; ++k)
                    if (T.js[j][k] != 0){
                        u64 a = (T.js[j][k] > 0) ? a0[j] : neg2(a0[j]);
                        hj[T.ja[j][k]] = fma2(a, a1[k], hj[T.ja[j][k]]);
                    }
            u64 lam2 = pk2(__ldg(refmv + (size_t)pa*16 + 15), __ldg(refmv + (size_t)(pa+1)*16 + 15));
            #pragma unroll
            for (int j = 0; j < 16; ++j) hj[j] = mul2(hj[j], lam2);
            __syncwarp();
            ulonglong2* h0 = (ulonglong2*)(xph + o*36);
            ulonglong2* h1 = (ulonglong2*)(xph + (16+o)*36);
            #pragma unroll
            for (int t = 0; t < 8; ++t){
                h0[t] = make_ulonglong2(hg[2*t], hg[2*t+1]);
                h1[t] = make_ulonglong2(hj[2*t], hj[2*t+1]);
            }
        }
        __syncwarp();

        {
            const u64* wt = (const u64*)(sm + OFF_WOM);
            #pragma unroll
            for (int j = 0; j < 16; ++j){ a0[j]=0ull; a1[j]=0ull; }
            #pragma unroll 1
            for (int i = 0; i < 32; ++i){
                const u64* wi = wt + i*144;
                u64 x2[16];
                const ulonglong2* xp = (const ulonglong2*)(xph + i*36);
                #pragma unroll
                for (int t = 0; t < 8; ++t){ ulonglong2 v = xp[t]; x2[2*t]=v.x; x2[2*t+1]=v.y; }
                float wa, wb;
                unpk2(wi[0*16+o],wa,wb); apply_b2<0>(wa,wb,x2,a0,a1);
                unpk2(wi[1*16+o],wa,wb); apply_b2<1>(wa,wb,x2,a0,a1);
                unpk2(wi[2*16+o],wa,wb); apply_b2<2>(wa,wb,x2,a0,a1);
                unpk2(wi[3*16+o],wa,wb); apply_b2<3>(wa,wb,x2,a0,a1);
                unpk2(wi[4*16+o],wa,wb); apply_b2<4>(wa,wb,x2,a0,a1);
                unpk2(wi[5*16+o],wa,wb); apply_b2<5>(wa,wb,x2,a0,a1);
                unpk2(wi[6*16+o],wa,wb); apply_b2<6>(wa,wb,x2,a0,a1);
                unpk2(wi[7*16+o],wa,wb); apply_b2<7>(wa,wb,x2,a0,a1);
                unpk2(wi[8*16+o],wa,wb); apply_b2<8>(wa,wb,x2,a0,a1);
            }
            #pragma unroll 4
            for (int s2 = 0; s2 < 32; ++s2){
                float4 w = __ldg((const float4*)(g_ws2m + (s2*16 + o)*4));
                float2 va = __ldg((const float2*)sc4 + s2);
                float2 vb = __ldg((const float2*)(sc4 + 64) + s2);
                u64 sva = pk2(va.x, vb.x), svb = pk2(va.y, vb.y);
                a0[0]=fma2(dup2(w.x),sva,a0[0]); a1[0]=fma2(dup2(w.y),sva,a1[0]);
                a0[0]=fma2(dup2(w.z),svb,a0[0]); a1[0]=fma2(dup2(w.w),svb,a1[0]);
            }
            float v0[16], v1[16], v2[16], v3[16];
            #pragma unroll
            for (int j = 0; j < 16; ++j){ unpk2(a0[j],v0[j],v1[j]); unpk2(a1[j],v2[j],v3[j]); }
            float* opA = out + ((size_t)pa*32 + o)*16;
            float* opC = out + ((size_t)pa*32 + o + 16)*16;
            #pragma unroll
            for (int j = 0; j < 16; j += 4){
                *(float4*)(opA + j)       = make_float4(v0[j],v0[j+1],v0[j+2],v0[j+3]);
                *(float4*)(opA + 512 + j) = make_float4(v1[j],v1[j+1],v1[j+2],v1[j+3]);
                *(float4*)(opC + j)       = make_float4(v2[j],v2[j+1],v2[j+2],v2[j+3]);
                *(float4*)(opC + 512 + j) = make_float4(v3[j],v3[j+1],v3[j+2],v3[j+3]);
            }
        }

        u64 as[2][2] = {{0ull,0ull},{0ull,0ull}};
        #pragma unroll
        for (int c2 = 0; c2 < 16; ++c2){
            float4 w = __ldg((const float4*)(g_wm2s + (c2*32 + lane)*4));
            u64 dwx=dup2(w.x), dwy=dup2(w.y), dwz=dup2(w.z), dww=dup2(w.w);
            const int re = 2*c2, ro = 2*c2+1;
            #pragma unroll
            for (int pk = 0; pk < 2; ++pk){
                u64 hev = *(const u64*)(xs + pk*PSTRIDE + re*36);
                u64 hod = *(const u64*)(xs + pk*PSTRIDE + ro*36);
                as[pk][0]=fma2(dwx,hev,as[pk][0]); as[pk][1]=fma2(dwy,hev,as[pk][1]);
                as[pk][0]=fma2(dwz,hod,as[pk][0]); as[pk][1]=fma2(dww,hod,as[pk][1]);
            }
        }
        #pragma unroll 4
        for (int s2 = 0; s2 < 32; ++s2){
            float4 w = __ldg((const float4*)(g_ws2s + (s2*32 + lane)*4));
            u64 dwx=dup2(w.x), dwy=dup2(w.y), dwz=dup2(w.z), dww=dup2(w.w);
            #pragma unroll
            for (int pk = 0; pk < 2; ++pk){
                const float* sb = sc + (size_t)(p0+2*pk)*64;
                float2 va = __ldg((const float2*)sb + s2);
                float2 vb = __ldg((const float2*)(sb + 64) + s2);
                u64 sva = pk2(va.x, vb.x), svb = pk2(va.y, vb.y);
                as[pk][0]=fma2(dwx,sva,as[pk][0]); as[pk][1]=fma2(dwy,sva,as[pk][1]);
                as[pk][0]=fma2(dwz,svb,as[pk][0]); as[pk][1]=fma2(dww,svb,as[pk][1]);
            }
        }
        #pragma unroll
        for (int pk = 0; pk < 2; ++pk){
            const int pb = p0 + 2*pk;
            float x0,x1,y0,y1;
            unpk2(as[pk][0],x0,x1); unpk2(as[pk][1],y0,y1);
            outs[(size_t)pb*64 + lane]        = x0;
            outs[(size_t)(pb+1)*64 + lane]    = x1;
            outs[(size_t)pb*64 + 32 + lane]   = y0;
            outs[(size_t)(pb+1)*64 + 32 + lane] = y1;
        }
    }
}

extern "C" void kernel_launch(void* const* d_in, const int* in_sizes, int n_in,
                              void* d_out, int out_size)
{
    const float* mv    = (const float*)d_in[0];
    const float* refmv = (const float*)d_in[1];
    const float* sc    = (const float*)d_in[2];
    const float* wLmv  = (const float*)d_in[6];
    const float* wLs   = (const float*)d_in[7];
    const float* wRmv  = (const float*)d_in[8];
    const float* wRs   = (const float*)d_in[9];
    const float* wJLmv = (const float*)d_in[10];
    const float* wJLs  = (const float*)d_in[11];
    const float* wJRmv = (const float*)d_in[12];
    const float* wJRs  = (const float*)d_in[13];
    const float* wOmv  = (const float*)d_in[14];
    const float* wOs2m = (const float*)d_in[15];
    const float* wM2s  = (const float*)d_in[16];
    const float* wS2s  = (const float*)d_in[17];
    float* out = (float*)d_out;

    const int P = in_sizes[0] / 512;
    const int quads = P / 4;
    int sms = 148;
    cudaDeviceGetAttribute(&sms, cudaDevAttrMultiProcessorCount, 0);

    repack_kernel<<<8, 256>>>(wLs, wRs, wJLs, wJRs, wOs2m, wM2s, wS2s);

    const size_t smem = (size_t)SMEMF * sizeof(float);
    cudaFuncSetAttribute(fused_kernel, cudaFuncAttributeMaxDynamicSharedMemorySize, (int)smem);
    fused_kernel<<<sms, NTHR, smem>>>(mv, refmv, sc, wLmv, wRmv, wJLmv, wJRmv, wOmv,
                                      out, quads, P);
}

// round 10
// speedup vs baseline: 1.1671x; 1.0549x over previous
#include <cuda_runtime.h>
#include <cuda_fp16.h>

#define NWARP 14
#define NTHR  (NWARP*32)
typedef unsigned long long u64;

__host__ __device__ constexpr int ga_popc(int x){ return (x&1)+((x>>1)&1)+((x>>2)&1)+((x>>3)&1); }
__host__ __device__ constexpr int ga_mask(int i){
    return i==0?0: i==1?1: i==2?2: i==3?4: i==4?8: i==5?3: i==6?5: i==7?9:
           i==8?6: i==9?10: i==10?12: i==11?7: i==12?11: i==13?13: i==14?14: 15;
}
__host__ __device__ constexpr int ga_idx(int m){
    return m==0?0: m==1?1: m==2?2: m==4?3: m==8?4: m==3?5: m==5?6: m==9?7:
           m==6?8: m==10?9: m==12?10: m==7?11: m==11?12: m==13?13: m==14?14: 15;
}
__host__ __device__ constexpr int ga_grade(int i){ return ga_popc(ga_mask(i)); }
__host__ __device__ constexpr int ga_csign(int a, int b){
    int s = 0;
    for (int i = 0; i < 4; ++i) if ((b>>i)&1) s += ga_popc(a >> (i+1));
    return (s&1) ? -1 : 1;
}
__host__ __device__ constexpr int ga_dsign(int b){ return ga_csign(ga_mask(b), 15 ^ ga_mask(b)); }

struct GaTabs { signed char gs[16][16], gi[16][16], js[16][16], ja[16][16]; };
__host__ __device__ constexpr GaTabs ga_make(){
    GaTabs t{};
    for (int j = 0; j < 16; ++j)
        for (int k = 0; k < 16; ++k){
            int mj = ga_mask(j), mk = ga_mask(k);
            if (mj & mk & 1){ t.gs[j][k]=0; t.gi[j][k]=0; }
            else { t.gs[j][k]=(signed char)ga_csign(mj,mk); t.gi[j][k]=(signed char)ga_idx(mj^mk); }
            int jm = 15^mj, km = 15^mk;
            if (jm & km){ t.js[j][k]=0; t.ja[j][k]=0; }
            else {
                int im = jm^km;
                int s = ga_csign(im,15^im)*ga_csign(jm,km)*ga_dsign(j)*ga_dsign(k);
                t.js[j][k]=(signed char)s; t.ja[j][k]=(signed char)ga_idx(15^im);
            }
        }
    return t;
}

__device__ __forceinline__ u64 pk2(float a, float b){ u64 r; asm("mov.b64 %0,{%1,%2};":"=l"(r):"f"(a),"f"(b)); return r; }
__device__ __forceinline__ void unpk2(u64 v, float& a, float& b){ asm("mov.b64 {%0,%1},%2;":"=f"(a),"=f"(b):"l"(v)); }
__device__ __forceinline__ u64 dup2(float a){ u64 r; asm("mov.b64 %0,{%1,%1};":"=l"(r):"f"(a)); return r; }
__device__ __forceinline__ u64 fma2(u64 a, u64 b, u64 c){ u64 d; asm("fma.rn.f32x2 %0,%1,%2,%3;":"=l"(d):"l"(a),"l"(b),"l"(c)); return d; }
__device__ __forceinline__ u64 mul2(u64 a, u64 b){ u64 d; asm("mul.rn.f32x2 %0,%1,%2;":"=l"(d):"l"(a),"l"(b)); return d; }
__device__ __forceinline__ u64 neg2(u64 a){ return a ^ 0x8000000080000000ull; }
__device__ __forceinline__ float2 h22f2(__half2 h){ return __half22float2(h); }

template<int B>
__device__ __forceinline__ void apply_b2(float wa, float wb, const u64* x2, u64* a0, u64* a1){
    u64 w0 = dup2(wa), w1 = dup2(wb);
    #pragma unroll
    for (int j = 0; j < 16; ++j){
        if (B < 5){
            if (ga_grade(j) == B){ a0[j]=fma2(w0,x2[j],a0[j]); a1[j]=fma2(w1,x2[j],a1[j]); }
        } else {
            if (!(ga_mask(j)&1) && ga_grade(j) == B-5){
                const int jj = ga_idx(ga_mask(j)|1);
                a0[jj]=fma2(w0,x2[j],a0[jj]); a1[jj]=fma2(w1,x2[j],a1[jj]);
            }
        }
    }
}
template<int B>
__device__ __forceinline__ void apply_b1(float wv, const u64* x2, u64* a){
    u64 w = dup2(wv);
    #pragma unroll
    for (int j = 0; j < 16; ++j){
        if (B < 5){
            if (ga_grade(j) == B) a[j] = fma2(w, x2[j], a[j]);
        } else {
            if (!(ga_mask(j)&1) && ga_grade(j) == B-5){
                const int jj = ga_idx(ga_mask(j)|1);
                a[jj] = fma2(w, x2[j], a[jj]);
            }
        }
    }
}

// smem layout in float units
#define OFF_WMV   0            /* 9216 h2  : [i][b][lane] = (A[o],B[o])            */
#define OFF_WS    9216         /* 1024 ui2 : [s2][lane] = (h2(se0),h2(se1))        */
#define OFF_WOM   11264        /* 5120 h2  : [i][q][lane]                          */
#define OFF_WS2M  16384        /* 1024 h2  : [s2][lane] = (we,wo)                  */
#define OFF_WM2S  17408        /* 512 ui2  : [c2][lane]                            */
#define OFF_WS2S  18432        /* 1024 ui2 : [s2][lane]                            */
#define OFF_STG   20480
#define STGW      1280
#define SMEMF     (OFF_STG + NWARP*STGW)   /* 38400 fl = 153.6 KB */

__global__ void __launch_bounds__(NTHR, 1)
fused_kernel(const float* __restrict__ mv, const float* __restrict__ refmv,
             const float* __restrict__ sc,
             const float* __restrict__ wLmv, const float* __restrict__ wLs,
             const float* __restrict__ wRmv, const float* __restrict__ wRs,
             const float* __restrict__ wJLmv, const float* __restrict__ wJLs,
             const float* __restrict__ wJRmv, const float* __restrict__ wJRs,
             const float* __restrict__ wOmv,  const float* __restrict__ wOs2mv,
             const float* __restrict__ wM2s,  const float* __restrict__ wS2s,
             float* __restrict__ out, int pairsTotal, int P)
{
    extern __shared__ float sm[];
    const int tid = threadIdx.x, warp = tid>>5, lane = tid&31;

    // ---- weight repacks (fp32 -> fp16) ----
    {
        __half2* W = (__half2*)(sm + OFF_WMV);
        for (int idx = tid; idx < 9216; idx += NTHR){
            int l = idx & 31, t2 = idx >> 5, b = t2 % 9, i = t2 / 9, o = l & 15;
            const float* A = (l < 16) ? wLmv : wJLmv;
            const float* B = (l < 16) ? wRmv : wJRmv;
            W[idx] = __floats2half2_rn(A[(o*32+i)*9+b], B[(o*32+i)*9+b]);
        }
        __half2* WSX = (__half2*)(sm + OFF_WS);
        for (int idx = tid; idx < 2048; idx += NTHR){
            int se = idx & 1, l = (idx>>1) & 31, s2 = idx >> 6, o = l & 15;
            const float* T0 = (l<16) ? wLs : wJLs;
            const float* T1 = (l<16) ? wRs : wJRs;
            WSX[idx] = __floats2half2_rn(T0[o*64 + s2*2 + se], T1[o*64 + s2*2 + se]);
        }
        __half2* WO = (__half2*)(sm + OFF_WOM);
        for (int idx = tid; idx < 5120; idx += NTHR){
            int l = idx & 31, t2 = idx >> 5, q = t2 % 5, i = t2 / 5;
            float a = wOmv[(l*32+i)*9 + ((q<4) ? 2*q : 8)];
            float b = (q<4) ? wOmv[(l*32+i)*9 + 2*q+1] : 0.f;
            WO[idx] = __floats2half2_rn(a, b);
        }
        __half2* WS2 = (__half2*)(sm + OFF_WS2M);
        for (int idx = tid; idx < 1024; idx += NTHR){
            int l = idx & 31, s2 = idx >> 5;
            WS2[idx] = __floats2half2_rn(wOs2mv[l*64 + s2*2], wOs2mv[l*64 + s2*2 + 1]);
        }
        __half2* WM2 = (__half2*)(sm + OFF_WM2S);
        for (int idx = tid; idx < 1024; idx += NTHR){
            int k = idx & 1, l = (idx>>1) & 31, c2 = idx >> 6;
            WM2[idx] = __floats2half2_rn(wM2s[l*32 + c2*2 + k], wM2s[(l+32)*32 + c2*2 + k]);
        }
        __half2* WSS = (__half2*)(sm + OFF_WS2S);
        for (int idx = tid; idx < 2048; idx += NTHR){
            int k = idx & 1, l = (idx>>1) & 31, s2 = idx >> 6;
            WSS[idx] = __floats2half2_rn(wS2s[l*64 + s2*2 + k], wS2s[(l+32)*64 + s2*2 + k]);
        }
    }
    __syncthreads();

    float* xs = sm + OFF_STG + warp * STGW;   // [32][36] x/h + [64][2] scalars
    float* ss = xs + 1152;
    float* outs = out + (size_t)P * 512;
    const int gwarps = gridDim.x * NWARP;
    constexpr GaTabs T = ga_make();

    for (int pair = blockIdx.x*NWARP + warp; pair < pairsTotal; pair += gwarps){
        const int p0 = pair * 2;

        __syncwarp();
        // stage x interleaved: xs[i*36 + j*2 + p]
        {
            const float4* s0 = (const float4*)(mv + (size_t)p0 * 512);
            const float4* s1 = s0 + 128;
            #pragma unroll
            for (int k = 0; k < 4; ++k){
                int q = lane + 32*k;
                float4 a = s0[q], b = s1[q];
                int i = q >> 2, j0 = (q & 3) * 4;
                float* dst = xs + i*36 + j0*2;
                *(u64*)(dst + 0) = pk2(a.x, b.x);
                *(u64*)(dst + 2) = pk2(a.y, b.y);
                *(u64*)(dst + 4) = pk2(a.z, b.z);
                *(u64*)(dst + 6) = pk2(a.w, b.w);
            }
            int p = lane >> 4, q = lane & 15;
            float4 v = ((const float4*)(sc + (size_t)(p0 + p)*64))[q];
            ss[(q*4 + 0)*2 + p] = v.x;
            ss[(q*4 + 1)*2 + p] = v.y;
            ss[(q*4 + 2)*2 + p] = v.z;
            ss[(q*4 + 3)*2 + p] = v.w;
        }
        __syncwarp();

        // phase 1: paired equi_linears
        u64 acc0[16], acc1[16];
        #pragma unroll
        for (int j = 0; j < 16; ++j){ acc0[j] = 0ull; acc1[j] = 0ull; }

        #pragma unroll 2
        for (int i = 0; i < 32; ++i){
            u64 x2[16];
            {
                const ulonglong2* xr = (const ulonglong2*)(xs + i*36);
                #pragma unroll
                for (int t = 0; t < 8; ++t){ ulonglong2 v = xr[t]; x2[2*t] = v.x; x2[2*t+1] = v.y; }
            }
            const __half2* wr = (const __half2*)(sm + OFF_WMV) + i*288;
            float2 w;
            w = h22f2(wr[0*32+lane]); apply_b2<0>(w.x, w.y, x2, acc0, acc1);
            w = h22f2(wr[1*32+lane]); apply_b2<1>(w.x, w.y, x2, acc0, acc1);
            w = h22f2(wr[2*32+lane]); apply_b2<2>(w.x, w.y, x2, acc0, acc1);
            w = h22f2(wr[3*32+lane]); apply_b2<3>(w.x, w.y, x2, acc0, acc1);
            w = h22f2(wr[4*32+lane]); apply_b2<4>(w.x, w.y, x2, acc0, acc1);
            w = h22f2(wr[5*32+lane]); apply_b2<5>(w.x, w.y, x2, acc0, acc1);
            w = h22f2(wr[6*32+lane]); apply_b2<6>(w.x, w.y, x2, acc0, acc1);
            w = h22f2(wr[7*32+lane]); apply_b2<7>(w.x, w.y, x2, acc0, acc1);
            w = h22f2(wr[8*32+lane]); apply_b2<8>(w.x, w.y, x2, acc0, acc1);
        }
        // scalar contribution -> component 0
        #pragma unroll 4
        for (int s2i = 0; s2i < 32; ++s2i){
            uint2 u = ((const uint2*)(sm + OFF_WS))[s2i*32 + lane];
            float2 w01 = h22f2(*(__half2*)&u.x);
            float2 w23 = h22f2(*(__half2*)&u.y);
            ulonglong2 sv = *(const ulonglong2*)(ss + s2i*4);
            acc0[0] = fma2(dup2(w01.x), sv.x, acc0[0]);
            acc1[0] = fma2(dup2(w01.y), sv.x, acc1[0]);
            acc0[0] = fma2(dup2(w23.x), sv.y, acc0[0]);
            acc1[0] = fma2(dup2(w23.y), sv.y, acc1[0]);
        }

        // bilinears (both operands local)
        u64 h2[16];
        #pragma unroll
        for (int j = 0; j < 16; ++j) h2[j] = 0ull;

        if (lane < 16){
            #pragma unroll
            for (int j = 0; j < 16; ++j)
                #pragma unroll
                for (int k = 0; k < 16; ++k)
                    if (T.gs[j][k] != 0){
                        u64 a = (T.gs[j][k] > 0) ? acc0[j] : neg2(acc0[j]);
                        h2[T.gi[j][k]] = fma2(a, acc1[k], h2[T.gi[j][k]]);
                    }
        } else {
            u64 lam2 = pk2(refmv[(size_t)p0*16 + 15], refmv[(size_t)(p0+1)*16 + 15]);
            #pragma unroll
            for (int j = 0; j < 16; ++j)
                #pragma unroll
                for (int k = 0; k < 16; ++k)
                    if (T.js[j][k] != 0){
                        u64 a = (T.js[j][k] > 0) ? acc0[j] : neg2(acc0[j]);
                        h2[T.ja[j][k]] = fma2(a, acc1[k], h2[T.ja[j][k]]);
                    }
            #pragma unroll
            for (int j = 0; j < 16; ++j) h2[j] = mul2(h2[j], lam2);
        }

        __syncwarp();
        {
            float* hr = xs + lane*36;
            #pragma unroll
            for (int j = 0; j < 16; ++j) *(u64*)(hr + j*2) = h2[j];
        }
        __syncwarp();

        // phase 2: output equi_linear (o = lane)
        u64 ao[16];
        #pragma unroll
        for (int j = 0; j < 16; ++j) ao[j] = 0ull;

        #pragma unroll 2
        for (int i = 0; i < 32; ++i){
            u64 x2[16];
            {
                const ulonglong2* xr = (const ulonglong2*)(xs + i*36);
                #pragma unroll
                for (int t = 0; t < 8; ++t){ ulonglong2 v = xr[t]; x2[2*t] = v.x; x2[2*t+1] = v.y; }
            }
            const __half2* gr = (const __half2*)(sm + OFF_WOM) + i*160;
            float2 g01 = h22f2(gr[0*32+lane]);
            float2 g23 = h22f2(gr[1*32+lane]);
            float2 g45 = h22f2(gr[2*32+lane]);
            float2 g67 = h22f2(gr[3*32+lane]);
            float2 g8x = h22f2(gr[4*32+lane]);
            apply_b1<0>(g01.x, x2, ao);
            apply_b1<1>(g01.y, x2, ao);
            apply_b1<2>(g23.x, x2, ao);
            apply_b1<3>(g23.y, x2, ao);
            apply_b1<4>(g45.x, x2, ao);
            apply_b1<5>(g45.y, x2, ao);
            apply_b1<6>(g67.x, x2, ao);
            apply_b1<7>(g67.y, x2, ao);
            apply_b1<8>(g8x.x, x2, ao);
        }
        // scalars -> component 0
        #pragma unroll 4
        for (int s2i = 0; s2i < 32; ++s2i){
            float2 w = h22f2(((const __half2*)(sm + OFF_WS2M))[s2i*32 + lane]);
            ulonglong2 sv = *(const ulonglong2*)(ss + s2i*4);
            ao[0] = fma2(dup2(w.x), sv.x, ao[0]);
            ao[0] = fma2(dup2(w.y), sv.y, ao[0]);
        }
        // store out_mv
        {
            float v0[16], v1[16];
            #pragma unroll
            for (int j = 0; j < 16; ++j) unpk2(ao[j], v0[j], v1[j]);
            float* op0 = out + ((size_t)p0*32 + lane)*16;
            float* op1 = op0 + 512;
            #pragma unroll
            for (int j = 0; j < 16; j += 4){
                *(float4*)(op0 + j) = make_float4(v0[j], v0[j+1], v0[j+2], v0[j+3]);
                *(float4*)(op1 + j) = make_float4(v1[j], v1[j+1], v1[j+2], v1[j+3]);
            }
        }

        // out_s: lane owns outputs (lane, lane+32)
        u64 as0 = 0ull, as1 = 0ull;
        #pragma unroll 4
        for (int c2 = 0; c2 < 16; ++c2){
            uint2 u = ((const uint2*)(sm + OFF_WM2S))[c2*32 + lane];
            float2 w01 = h22f2(*(__half2*)&u.x);
            float2 w23 = h22f2(*(__half2*)&u.y);
            u64 hev = *(const u64*)(xs + (2*c2    )*36);
            u64 hod = *(const u64*)(xs + (2*c2 + 1)*36);
            as0 = fma2(dup2(w01.x), hev, as0);
            as1 = fma2(dup2(w01.y), hev, as1);
            as0 = fma2(dup2(w23.x), hod, as0);
            as1 = fma2(dup2(w23.y), hod, as1);
        }
        #pragma unroll 4
        for (int s2i = 0; s2i < 32; ++s2i){
            uint2 u = ((const uint2*)(sm + OFF_WS2S))[s2i*32 + lane];
            float2 w01 = h22f2(*(__half2*)&u.x);
            float2 w23 = h22f2(*(__half2*)&u.y);
            ulonglong2 sv = *(const ulonglong2*)(ss + s2i*4);
            as0 = fma2(dup2(w01.x), sv.x, as0);
            as1 = fma2(dup2(w01.y), sv.x, as1);
            as0 = fma2(dup2(w23.x), sv.y, as0);
            as1 = fma2(dup2(w23.y), sv.y, as1);
        }
        {
            float a0, a1, b0, b1;
            unpk2(as0, a0, a1);
            unpk2(as1, b0, b1);
            outs[(size_t)p0*64 + lane]          = a0;
            outs[(size_t)(p0+1)*64 + lane]      = a1;
            outs[(size_t)p0*64 + 32 + lane]     = b0;
            outs[(size_t)(p0+1)*64 + 32 + lane] = b1;
        }
    }
}

extern "C" void kernel_launch(void* const* d_in, const int* in_sizes, int n_in,
                              void* d_out, int out_size)
{
    const float* mv    = (const float*)d_in[0];
    const float* refmv = (const float*)d_in[1];
    const float* sc    = (const float*)d_in[2];
    const float* wLmv  = (const float*)d_in[6];
    const float* wLs   = (const float*)d_in[7];
    const float* wRmv  = (const float*)d_in[8];
    const float* wRs   = (const float*)d_in[9];
    const float* wJLmv = (const float*)d_in[10];
    const float* wJLs  = (const float*)d_in[11];
    const float* wJRmv = (const float*)d_in[12];
    const float* wJRs  = (const float*)d_in[13];
    const float* wOmv  = (const float*)d_in[14];
    const float* wOs2m = (const float*)d_in[15];
    const float* wM2s  = (const float*)d_in[16];
    const float* wS2s  = (const float*)d_in[17];
    float* out = (float*)d_out;

    const int P = in_sizes[0] / 512;
    const int pairs = P / 2;

    int sms = 148;
    cudaDeviceGetAttribute(&sms, cudaDevAttrMultiProcessorCount, 0);

    const size_t smem = (size_t)SMEMF * sizeof(float);
    cudaFuncSetAttribute(fused_kernel, cudaFuncAttributeMaxDynamicSharedMemorySize, (int)smem);

    fused_kernel<<<sms, NTHR, smem>>>(mv, refmv, sc,
                                      wLmv, wLs, wRmv, wRs,
                                      wJLmv, wJLs, wJRmv, wJRs,
                                      wOmv, wOs2m, wM2s, wS2s,
                                      out, pairs, P);
}

// round 11
// speedup vs baseline: 1.2241x; 1.0488x over previous
#include <cuda_runtime.h>
#include <cuda_fp16.h>

#define NWARP 16
#define NTHR  (NWARP*32)
typedef unsigned long long u64;

__host__ __device__ constexpr int ga_popc(int x){ return (x&1)+((x>>1)&1)+((x>>2)&1)+((x>>3)&1); }
__host__ __device__ constexpr int ga_mask(int i){
    return i==0?0: i==1?1: i==2?2: i==3?4: i==4?8: i==5?3: i==6?5: i==7?9:
           i==8?6: i==9?10: i==10?12: i==11?7: i==12?11: i==13?13: i==14?14: 15;
}
__host__ __device__ constexpr int ga_idx(int m){
    return m==0?0: m==1?1: m==2?2: m==4?3: m==8?4: m==3?5: m==5?6: m==9?7:
           m==6?8: m==10?9: m==12?10: m==7?11: m==11?12: m==13?13: m==14?14: 15;
}
__host__ __device__ constexpr int ga_grade(int i){ return ga_popc(ga_mask(i)); }
__host__ __device__ constexpr int ga_csign(int a, int b){
    int s = 0;
    for (int i = 0; i < 4; ++i) if ((b>>i)&1) s += ga_popc(a >> (i+1));
    return (s&1) ? -1 : 1;
}
__host__ __device__ constexpr int ga_dsign(int b){ return ga_csign(ga_mask(b), 15 ^ ga_mask(b)); }

struct GaTabs { signed char gs[16][16], gi[16][16], js[16][16], ja[16][16]; };
__host__ __device__ constexpr GaTabs ga_make(){
    GaTabs t{};
    for (int j = 0; j < 16; ++j)
        for (int k = 0; k < 16; ++k){
            int mj = ga_mask(j), mk = ga_mask(k);
            if (mj & mk & 1){ t.gs[j][k]=0; t.gi[j][k]=0; }
            else { t.gs[j][k]=(signed char)ga_csign(mj,mk); t.gi[j][k]=(signed char)ga_idx(mj^mk); }
            int jm = 15^mj, km = 15^mk;
            if (jm & km){ t.js[j][k]=0; t.ja[j][k]=0; }
            else {
                int im = jm^km;
                int s = ga_csign(im,15^im)*ga_csign(jm,km)*ga_dsign(j)*ga_dsign(k);
                t.js[j][k]=(signed char)s; t.ja[j][k]=(signed char)ga_idx(15^im);
            }
        }
    return t;
}

__device__ __forceinline__ u64 pk2(float a, float b){ u64 r; asm("mov.b64 %0,{%1,%2};":"=l"(r):"f"(a),"f"(b)); return r; }
__device__ __forceinline__ void unpk2(u64 v, float& a, float& b){ asm("mov.b64 {%0,%1},%2;":"=f"(a),"=f"(b):"l"(v)); }
__device__ __forceinline__ u64 dup2(float a){ u64 r; asm("mov.b64 %0,{%1,%1};":"=l"(r):"f"(a)); return r; }
__device__ __forceinline__ u64 fma2(u64 a, u64 b, u64 c){ u64 d; asm("fma.rn.f32x2 %0,%1,%2,%3;":"=l"(d):"l"(a),"l"(b),"l"(c)); return d; }
__device__ __forceinline__ u64 mul2(u64 a, u64 b){ u64 d; asm("mul.rn.f32x2 %0,%1,%2;":"=l"(d):"l"(a),"l"(b)); return d; }
__device__ __forceinline__ u64 neg2(u64 a){ return a ^ 0x8000000080000000ull; }
__device__ __forceinline__ float2 h22f2(__half2 h){ return __half22float2(h); }

template<int B>
__device__ __forceinline__ void apply_b2(float wa, float wb, const u64* x2, u64* a0, u64* a1){
    u64 w0 = dup2(wa), w1 = dup2(wb);
    #pragma unroll
    for (int j = 0; j < 16; ++j){
        if (B < 5){
            if (ga_grade(j) == B){ a0[j]=fma2(w0,x2[j],a0[j]); a1[j]=fma2(w1,x2[j],a1[j]); }
        } else {
            if (!(ga_mask(j)&1) && ga_grade(j) == B-5){
                const int jj = ga_idx(ga_mask(j)|1);
                a0[jj]=fma2(w0,x2[j],a0[jj]); a1[jj]=fma2(w1,x2[j],a1[jj]);
            }
        }
    }
}
template<int B>
__device__ __forceinline__ void apply_b1(float wv, const u64* x2, u64* a){
    u64 w = dup2(wv);
    #pragma unroll
    for (int j = 0; j < 16; ++j){
        if (B < 5){
            if (ga_grade(j) == B) a[j] = fma2(w, x2[j], a[j]);
        } else {
            if (!(ga_mask(j)&1) && ga_grade(j) == B-5){
                const int jj = ga_idx(ga_mask(j)|1);
                a[jj] = fma2(w, x2[j], a[jj]);
            }
        }
    }
}

// smem layout in float units
#define OFF_WMV   0
#define OFF_WS    9216
#define OFF_WOM   11264
#define OFF_WS2M  16384
#define OFF_WM2S  17408
#define OFF_WS2S  18432
#define OFF_STG   20480
#define STGW      1280
#define SMEMF     (OFF_STG + NWARP*STGW)   /* 40960 fl = 163.8 KB */

__global__ void __launch_bounds__(NTHR, 1)
fused_kernel(const float* __restrict__ mv, const float* __restrict__ refmv,
             const float* __restrict__ sc,
             const float* __restrict__ wLmv, const float* __restrict__ wLs,
             const float* __restrict__ wRmv, const float* __restrict__ wRs,
             const float* __restrict__ wJLmv, const float* __restrict__ wJLs,
             const float* __restrict__ wJRmv, const float* __restrict__ wJRs,
             const float* __restrict__ wOmv,  const float* __restrict__ wOs2mv,
             const float* __restrict__ wM2s,  const float* __restrict__ wS2s,
             float* __restrict__ out, int pairsTotal, int P)
{
    extern __shared__ float sm[];
    const int tid = threadIdx.x, warp = tid>>5, lane = tid&31;

    // ---- weight repacks (fp32 -> fp16) ----
    {
        __half2* W = (__half2*)(sm + OFF_WMV);
        for (int idx = tid; idx < 9216; idx += NTHR){
            int l = idx & 31, t2 = idx >> 5, b = t2 % 9, i = t2 / 9, o = l & 15;
            const float* A = (l < 16) ? wLmv : wJLmv;
            const float* B = (l < 16) ? wRmv : wJRmv;
            W[idx] = __floats2half2_rn(A[(o*32+i)*9+b], B[(o*32+i)*9+b]);
        }
        __half2* WSX = (__half2*)(sm + OFF_WS);
        for (int idx = tid; idx < 2048; idx += NTHR){
            int se = idx & 1, l = (idx>>1) & 31, s2 = idx >> 6, o = l & 15;
            const float* T0 = (l<16) ? wLs : wJLs;
            const float* T1 = (l<16) ? wRs : wJRs;
            WSX[idx] = __floats2half2_rn(T0[o*64 + s2*2 + se], T1[o*64 + s2*2 + se]);
        }
        __half2* WO = (__half2*)(sm + OFF_WOM);
        for (int idx = tid; idx < 5120; idx += NTHR){
            int l = idx & 31, t2 = idx >> 5, q = t2 % 5, i = t2 / 5;
            float a = wOmv[(l*32+i)*9 + ((q<4) ? 2*q : 8)];
            float b = (q<4) ? wOmv[(l*32+i)*9 + 2*q+1] : 0.f;
            WO[idx] = __floats2half2_rn(a, b);
        }
        __half2* WS2 = (__half2*)(sm + OFF_WS2M);
        for (int idx = tid; idx < 1024; idx += NTHR){
            int l = idx & 31, s2 = idx >> 5;
            WS2[idx] = __floats2half2_rn(wOs2mv[l*64 + s2*2], wOs2mv[l*64 + s2*2 + 1]);
        }
        __half2* WM2 = (__half2*)(sm + OFF_WM2S);
        for (int idx = tid; idx < 1024; idx += NTHR){
            int k = idx & 1, l = (idx>>1) & 31, c2 = idx >> 6;
            WM2[idx] = __floats2half2_rn(wM2s[l*32 + c2*2 + k], wM2s[(l+32)*32 + c2*2 + k]);
        }
        __half2* WSS = (__half2*)(sm + OFF_WS2S);
        for (int idx = tid; idx < 2048; idx += NTHR){
            int k = idx & 1, l = (idx>>1) & 31, s2 = idx >> 6;
            WSS[idx] = __floats2half2_rn(wS2s[l*64 + s2*2 + k], wS2s[(l+32)*64 + s2*2 + k]);
        }
    }
    __syncthreads();

    float* xs = sm + OFF_STG + warp * STGW;   // [32][36] x/h + [64][2] scalars
    float* ss = xs + 1152;
    float* outs = out + (size_t)P * 512;
    const int gwarps = gridDim.x * NWARP;
    constexpr GaTabs T = ga_make();

    for (int pair = blockIdx.x*NWARP + warp; pair < pairsTotal; pair += gwarps){
        const int p0 = pair * 2;

        __syncwarp();
        // stage x interleaved: xs[i*36 + j*2 + p]
        {
            const float4* s0 = (const float4*)(mv + (size_t)p0 * 512);
            const float4* s1 = s0 + 128;
            #pragma unroll
            for (int k = 0; k < 4; ++k){
                int q = lane + 32*k;
                float4 a = s0[q], b = s1[q];
                int i = q >> 2, j0 = (q & 3) * 4;
                float* dst = xs + i*36 + j0*2;
                *(u64*)(dst + 0) = pk2(a.x, b.x);
                *(u64*)(dst + 2) = pk2(a.y, b.y);
                *(u64*)(dst + 4) = pk2(a.z, b.z);
                *(u64*)(dst + 6) = pk2(a.w, b.w);
            }
            int p = lane >> 4, q = lane & 15;
            float4 v = ((const float4*)(sc + (size_t)(p0 + p)*64))[q];
            ss[(q*4 + 0)*2 + p] = v.x;
            ss[(q*4 + 1)*2 + p] = v.y;
            ss[(q*4 + 2)*2 + p] = v.z;
            ss[(q*4 + 3)*2 + p] = v.w;
        }
        __syncwarp();

        // phase 1: paired equi_linears
        u64 acc0[16], acc1[16];
        #pragma unroll
        for (int j = 0; j < 16; ++j){ acc0[j] = 0ull; acc1[j] = 0ull; }

        #pragma unroll 2
        for (int i = 0; i < 32; ++i){
            u64 x2[16];
            {
                const ulonglong2* xr = (const ulonglong2*)(xs + i*36);
                #pragma unroll
                for (int t = 0; t < 8; ++t){ ulonglong2 v = xr[t]; x2[2*t] = v.x; x2[2*t+1] = v.y; }
            }
            const __half2* wr = (const __half2*)(sm + OFF_WMV) + i*288;
            float2 w;
            w = h22f2(wr[0*32+lane]); apply_b2<0>(w.x, w.y, x2, acc0, acc1);
            w = h22f2(wr[1*32+lane]); apply_b2<1>(w.x, w.y, x2, acc0, acc1);
            w = h22f2(wr[2*32+lane]); apply_b2<2>(w.x, w.y, x2, acc0, acc1);
            w = h22f2(wr[3*32+lane]); apply_b2<3>(w.x, w.y, x2, acc0, acc1);
            w = h22f2(wr[4*32+lane]); apply_b2<4>(w.x, w.y, x2, acc0, acc1);
            w = h22f2(wr[5*32+lane]); apply_b2<5>(w.x, w.y, x2, acc0, acc1);
            w = h22f2(wr[6*32+lane]); apply_b2<6>(w.x, w.y, x2, acc0, acc1);
            w = h22f2(wr[7*32+lane]); apply_b2<7>(w.x, w.y, x2, acc0, acc1);
            w = h22f2(wr[8*32+lane]); apply_b2<8>(w.x, w.y, x2, acc0, acc1);
        }
        // scalar contribution -> component 0
        #pragma unroll 4
        for (int s2i = 0; s2i < 32; ++s2i){
            uint2 u = ((const uint2*)(sm + OFF_WS))[s2i*32 + lane];
            float2 w01 = h22f2(*(__half2*)&u.x);
            float2 w23 = h22f2(*(__half2*)&u.y);
            ulonglong2 sv = *(const ulonglong2*)(ss + s2i*4);
            acc0[0] = fma2(dup2(w01.x), sv.x, acc0[0]);
            acc1[0] = fma2(dup2(w01.y), sv.x, acc1[0]);
            acc0[0] = fma2(dup2(w23.x), sv.y, acc0[0]);
            acc1[0] = fma2(dup2(w23.y), sv.y, acc1[0]);
        }

        // bilinears (both operands local)
        u64 h2[16];
        #pragma unroll
        for (int j = 0; j < 16; ++j) h2[j] = 0ull;

        if (lane < 16){
            #pragma unroll
            for (int j = 0; j < 16; ++j)
                #pragma unroll
                for (int k = 0; k < 16; ++k)
                    if (T.gs[j][k] != 0){
                        u64 a = (T.gs[j][k] > 0) ? acc0[j] : neg2(acc0[j]);
                        h2[T.gi[j][k]] = fma2(a, acc1[k], h2[T.gi[j][k]]);
                    }
        } else {
            u64 lam2 = pk2(refmv[(size_t)p0*16 + 15], refmv[(size_t)(p0+1)*16 + 15]);
            #pragma unroll
            for (int j = 0; j < 16; ++j)
                #pragma unroll
                for (int k = 0; k < 16; ++k)
                    if (T.js[j][k] != 0){
                        u64 a = (T.js[j][k] > 0) ? acc0[j] : neg2(acc0[j]);
                        h2[T.ja[j][k]] = fma2(a, acc1[k], h2[T.ja[j][k]]);
                    }
            #pragma unroll
            for (int j = 0; j < 16; ++j) h2[j] = mul2(h2[j], lam2);
        }

        __syncwarp();
        {
            float* hr = xs + lane*36;
            #pragma unroll
            for (int j = 0; j < 16; ++j) *(u64*)(hr + j*2) = h2[j];
        }
        __syncwarp();

        // phase 2: output equi_linear (o = lane)
        u64 ao[16];
        #pragma unroll
        for (int j = 0; j < 16; ++j) ao[j] = 0ull;

        #pragma unroll 2
        for (int i = 0; i < 32; ++i){
            u64 x2[16];
            {
                const ulonglong2* xr = (const ulonglong2*)(xs + i*36);
                #pragma unroll
                for (int t = 0; t < 8; ++t){ ulonglong2 v = xr[t]; x2[2*t] = v.x; x2[2*t+1] = v.y; }
            }
            const __half2* gr = (const __half2*)(sm + OFF_WOM) + i*160;
            float2 g01 = h22f2(gr[0*32+lane]);
            float2 g23 = h22f2(gr[1*32+lane]);
            float2 g45 = h22f2(gr[2*32+lane]);
            float2 g67 = h22f2(gr[3*32+lane]);
            float2 g8x = h22f2(gr[4*32+lane]);
            apply_b1<0>(g01.x, x2, ao);
            apply_b1<1>(g01.y, x2, ao);
            apply_b1<2>(g23.x, x2, ao);
            apply_b1<3>(g23.y, x2, ao);
            apply_b1<4>(g45.x, x2, ao);
            apply_b1<5>(g45.y, x2, ao);
            apply_b1<6>(g67.x, x2, ao);
            apply_b1<7>(g67.y, x2, ao);
            apply_b1<8>(g8x.x, x2, ao);
        }
        // scalars -> component 0
        #pragma unroll 4
        for (int s2i = 0; s2i < 32; ++s2i){
            float2 w = h22f2(((const __half2*)(sm + OFF_WS2M))[s2i*32 + lane]);
            ulonglong2 sv = *(const ulonglong2*)(ss + s2i*4);
            ao[0] = fma2(dup2(w.x), sv.x, ao[0]);
            ao[0] = fma2(dup2(w.y), sv.y, ao[0]);
        }
        // store out_mv
        {
            float v0[16], v1[16];
            #pragma unroll
            for (int j = 0; j < 16; ++j) unpk2(ao[j], v0[j], v1[j]);
            float* op0 = out + ((size_t)p0*32 + lane)*16;
            float* op1 = op0 + 512;
            #pragma unroll
            for (int j = 0; j < 16; j += 4){
                *(float4*)(op0 + j) = make_float4(v0[j], v0[j+1], v0[j+2], v0[j+3]);
                *(float4*)(op1 + j) = make_float4(v1[j], v1[j+1], v1[j+2], v1[j+3]);
            }
        }

        // out_s: lane owns outputs (lane, lane+32)
        u64 as0 = 0ull, as1 = 0ull;
        #pragma unroll 4
        for (int c2 = 0; c2 < 16; ++c2){
            uint2 u = ((const uint2*)(sm + OFF_WM2S))[c2*32 + lane];
            float2 w01 = h22f2(*(__half2*)&u.x);
            float2 w23 = h22f2(*(__half2*)&u.y);
            u64 hev = *(const u64*)(xs + (2*c2    )*36);
            u64 hod = *(const u64*)(xs + (2*c2 + 1)*36);
            as0 = fma2(dup2(w01.x), hev, as0);
            as1 = fma2(dup2(w01.y), hev, as1);
            as0 = fma2(dup2(w23.x), hod, as0);
            as1 = fma2(dup2(w23.y), hod, as1);
        }
        #pragma unroll 4
        for (int s2i = 0; s2i < 32; ++s2i){
            uint2 u = ((const uint2*)(sm + OFF_WS2S))[s2i*32 + lane];
            float2 w01 = h22f2(*(__half2*)&u.x);
            float2 w23 = h22f2(*(__half2*)&u.y);
            ulonglong2 sv = *(const ulonglong2*)(ss + s2i*4);
            as0 = fma2(dup2(w01.x), sv.x, as0);
            as1 = fma2(dup2(w01.y), sv.x, as1);
            as0 = fma2(dup2(w23.x), sv.y, as0);
            as1 = fma2(dup2(w23.y), sv.y, as1);
        }
        {
            float a0, a1, b0, b1;
            unpk2(as0, a0, a1);
            unpk2(as1, b0, b1);
            outs[(size_t)p0*64 + lane]          = a0;
            outs[(size_t)(p0+1)*64 + lane]      = a1;
            outs[(size_t)p0*64 + 32 + lane]     = b0;
            outs[(size_t)(p0+1)*64 + 32 + lane] = b1;
        }
    }
}

extern "C" void kernel_launch(void* const* d_in, const int* in_sizes, int n_in,
                              void* d_out, int out_size)
{
    const float* mv    = (const float*)d_in[0];
    const float* refmv = (const float*)d_in[1];
    const float* sc    = (const float*)d_in[2];
    const float* wLmv  = (const float*)d_in[6];
    const float* wLs   = (const float*)d_in[7];
    const float* wRmv  = (const float*)d_in[8];
    const float* wRs   = (const float*)d_in[9];
    const float* wJLmv = (const float*)d_in[10];
    const float* wJLs  = (const float*)d_in[11];
    const float* wJRmv = (const float*)d_in[12];
    const float* wJRs  = (const float*)d_in[13];
    const float* wOmv  = (const float*)d_in[14];
    const float* wOs2m = (const float*)d_in[15];
    const float* wM2s  = (const float*)d_in[16];
    const float* wS2s  = (const float*)d_in[17];
    float* out = (float*)d_out;

    const int P = in_sizes[0] / 512;
    const int pairs = P / 2;

    int sms = 148;
    cudaDeviceGetAttribute(&sms, cudaDevAttrMultiProcessorCount, 0);

    const size_t smem = (size_t)SMEMF * sizeof(float);
    cudaFuncSetAttribute(fused_kernel, cudaFuncAttributeMaxDynamicSharedMemorySize, (int)smem);

    fused_kernel<<<sms, NTHR, smem>>>(mv, refmv, sc,
                                      wLmv, wLs, wRmv, wRs,
                                      wJLmv, wJLs, wJRmv, wJRs,
                                      wOmv, wOs2m, wM2s, wS2s,
                                      out, pairs, P);
}

// round 12
// speedup vs baseline: 1.2993x; 1.0614x over previous
#include <cuda_runtime.h>
#include <cuda_fp16.h>

#define NWARP 16
#define NTHR  (NWARP*32)
typedef unsigned long long u64;

__host__ __device__ constexpr int ga_popc(int x){ return (x&1)+((x>>1)&1)+((x>>2)&1)+((x>>3)&1); }
__host__ __device__ constexpr int ga_mask(int i){
    return i==0?0: i==1?1: i==2?2: i==3?4: i==4?8: i==5?3: i==6?5: i==7?9:
           i==8?6: i==9?10: i==10?12: i==11?7: i==12?11: i==13?13: i==14?14: 15;
}
__host__ __device__ constexpr int ga_idx(int m){
    return m==0?0: m==1?1: m==2?2: m==4?3: m==8?4: m==3?5: m==5?6: m==9?7:
           m==6?8: m==10?9: m==12?10: m==7?11: m==11?12: m==13?13: m==14?14: 15;
}
__host__ __device__ constexpr int ga_grade(int i){ return ga_popc(ga_mask(i)); }
__host__ __device__ constexpr int ga_csign(int a, int b){
    int s = 0;
    for (int i = 0; i < 4; ++i) if ((b>>i)&1) s += ga_popc(a >> (i+1));
    return (s&1) ? -1 : 1;
}
__host__ __device__ constexpr int ga_dsign(int b){ return ga_csign(ga_mask(b), 15 ^ ga_mask(b)); }

struct GaTabs { signed char gs[16][16], gi[16][16], js[16][16], ja[16][16]; };
__host__ __device__ constexpr GaTabs ga_make(){
    GaTabs t{};
    for (int j = 0; j < 16; ++j)
        for (int k = 0; k < 16; ++k){
            int mj = ga_mask(j), mk = ga_mask(k);
            if (mj & mk & 1){ t.gs[j][k]=0; t.gi[j][k]=0; }
            else { t.gs[j][k]=(signed char)ga_csign(mj,mk); t.gi[j][k]=(signed char)ga_idx(mj^mk); }
            int jm = 15^mj, km = 15^mk;
            if (jm & km){ t.js[j][k]=0; t.ja[j][k]=0; }
            else {
                int im = jm^km;
                int s = ga_csign(im,15^im)*ga_csign(jm,km)*ga_dsign(j)*ga_dsign(k);
                t.js[j][k]=(signed char)s; t.ja[j][k]=(signed char)ga_idx(15^im);
            }
        }
    return t;
}

__device__ __forceinline__ u64 pk2(float a, float b){ u64 r; asm("mov.b64 %0,{%1,%2};":"=l"(r):"f"(a),"f"(b)); return r; }
__device__ __forceinline__ void unpk2(u64 v, float& a, float& b){ asm("mov.b64 {%0,%1},%2;":"=f"(a),"=f"(b):"l"(v)); }
__device__ __forceinline__ u64 dup2(float a){ u64 r; asm("mov.b64 %0,{%1,%1};":"=l"(r):"f"(a)); return r; }
__device__ __forceinline__ u64 fma2(u64 a, u64 b, u64 c){ u64 d; asm("fma.rn.f32x2 %0,%1,%2,%3;":"=l"(d):"l"(a),"l"(b),"l"(c)); return d; }
__device__ __forceinline__ u64 mul2(u64 a, u64 b){ u64 d; asm("mul.rn.f32x2 %0,%1,%2;":"=l"(d):"l"(a),"l"(b)); return d; }
__device__ __forceinline__ u64 neg2(u64 a){ return a ^ 0x8000000080000000ull; }
__device__ __forceinline__ float2 h2f(unsigned int u){ __half2 h = *(__half2*)&u; return __half22float2(h); }

template<int B>
__device__ __forceinline__ void apply_b2(float wa, float wb, const u64* x2, u64* a0, u64* a1){
    u64 w0 = dup2(wa), w1 = dup2(wb);
    #pragma unroll
    for (int j = 0; j < 16; ++j){
        if (B < 5){
            if (ga_grade(j) == B){ a0[j]=fma2(w0,x2[j],a0[j]); a1[j]=fma2(w1,x2[j],a1[j]); }
        } else {
            if (!(ga_mask(j)&1) && ga_grade(j) == B-5){
                const int jj = ga_idx(ga_mask(j)|1);
                a0[jj]=fma2(w0,x2[j],a0[jj]); a1[jj]=fma2(w1,x2[j],a1[jj]);
            }
        }
    }
}
template<int B>
__device__ __forceinline__ void apply_b1(float wv, const u64* x2, u64* a){
    u64 w = dup2(wv);
    #pragma unroll
    for (int j = 0; j < 16; ++j){
        if (B < 5){
            if (ga_grade(j) == B) a[j] = fma2(w, x2[j], a[j]);
        } else {
            if (!(ga_mask(j)&1) && ga_grade(j) == B-5){
                const int jj = ga_idx(ga_mask(j)|1);
                a[jj] = fma2(w, x2[j], a[jj]);
            }
        }
    }
}

// smem layout (float units)
#define OFF_WA    0       /* [i][lane] uint4  : b0..b3 half2  = 4096 fl */
#define OFF_WB    4096    /* [i][lane] uint4  : b4..b7 half2  = 4096 fl */
#define OFF_WC    8192    /* [i][lane] uint   : b8 half2      = 1024 fl */
#define OFF_WS    9216    /* [s2][lane] uint2                  = 2048 fl */
#define OFF_OA    11264   /* [i][lane] uint4  : q0..q3 half2  = 4096 fl */
#define OFF_OC    15360   /* [i][lane] uint   : b8 half2      = 1024 fl */
#define OFF_WS2M  16384   /* [s2][lane] half2                  = 1024 fl */
#define OFF_M2    17408   /* [i][lane] half2  : m2s weights    = 1024 fl */
#define OFF_WS2S  18432   /* [s2][lane] uint2                  = 2048 fl */
#define OFF_STG   20480
#define STGW      1280
#define SMEMF     (OFF_STG + NWARP*STGW)   /* 40960 fl = 163.8 KB */

__global__ void __launch_bounds__(NTHR, 1)
fused_kernel(const float* __restrict__ mv, const float* __restrict__ refmv,
             const float* __restrict__ sc,
             const float* __restrict__ wLmv, const float* __restrict__ wLs,
             const float* __restrict__ wRmv, const float* __restrict__ wRs,
             const float* __restrict__ wJLmv, const float* __restrict__ wJLs,
             const float* __restrict__ wJRmv, const float* __restrict__ wJRs,
             const float* __restrict__ wOmv,  const float* __restrict__ wOs2mv,
             const float* __restrict__ wM2s,  const float* __restrict__ wS2s,
             float* __restrict__ out, int pairsTotal, int P)
{
    extern __shared__ float sm[];
    const int tid = threadIdx.x, warp = tid>>5, lane = tid&31;

    // ---- weight repacks (fp32 -> fp16) ----
    {
        __half2* WA = (__half2*)(sm + OFF_WA);
        __half2* WB = (__half2*)(sm + OFF_WB);
        __half2* WC = (__half2*)(sm + OFF_WC);
        for (int idx = tid; idx < 1024; idx += NTHR){
            int i = idx >> 5, l = idx & 31, o = l & 15;
            const float* A = (l < 16) ? wLmv : wJLmv;
            const float* B = (l < 16) ? wRmv : wJRmv;
            int base = (o*32+i)*9;
            #pragma unroll
            for (int b = 0; b < 4; ++b){
                WA[idx*4 + b] = __floats2half2_rn(A[base+b],   B[base+b]);
                WB[idx*4 + b] = __floats2half2_rn(A[base+4+b], B[base+4+b]);
            }
            WC[idx] = __floats2half2_rn(A[base+8], B[base+8]);
        }
        __half2* WSX = (__half2*)(sm + OFF_WS);
        for (int idx = tid; idx < 2048; idx += NTHR){
            int se = idx & 1, l = (idx>>1) & 31, s2 = idx >> 6, o = l & 15;
            const float* T0 = (l<16) ? wLs : wJLs;
            const float* T1 = (l<16) ? wRs : wJRs;
            WSX[idx] = __floats2half2_rn(T0[o*64 + s2*2 + se], T1[o*64 + s2*2 + se]);
        }
        __half2* OA = (__half2*)(sm + OFF_OA);
        __half2* OC = (__half2*)(sm + OFF_OC);
        for (int idx = tid; idx < 1024; idx += NTHR){
            int i = idx >> 5, l = idx & 31;
            int base = (l*32+i)*9;
            #pragma unroll
            for (int q = 0; q < 4; ++q)
                OA[idx*4 + q] = __floats2half2_rn(wOmv[base+2*q], wOmv[base+2*q+1]);
            OC[idx] = __floats2half2_rn(wOmv[base+8], 0.f);
        }
        __half2* WS2 = (__half2*)(sm + OFF_WS2M);
        for (int idx = tid; idx < 1024; idx += NTHR){
            int l = idx & 31, s2 = idx >> 5;
            WS2[idx] = __floats2half2_rn(wOs2mv[l*64 + s2*2], wOs2mv[l*64 + s2*2 + 1]);
        }
        __half2* M2 = (__half2*)(sm + OFF_M2);
        for (int idx = tid; idx < 1024; idx += NTHR){
            int i = idx >> 5, l = idx & 31;
            M2[idx] = __floats2half2_rn(wM2s[l*32 + i], wM2s[(l+32)*32 + i]);
        }
        __half2* WSS = (__half2*)(sm + OFF_WS2S);
        for (int idx = tid; idx < 2048; idx += NTHR){
            int k = idx & 1, l = (idx>>1) & 31, s2 = idx >> 6;
            WSS[idx] = __floats2half2_rn(wS2s[l*64 + s2*2 + k], wS2s[(l+32)*64 + s2*2 + k]);
        }
    }
    __syncthreads();

    float* xs = sm + OFF_STG + warp * STGW;   // [32][36] x/h + [64][2] scalars
    float* ss = xs + 1152;
    float* outs = out + (size_t)P * 512;
    const int gwarps = gridDim.x * NWARP;
    constexpr GaTabs T = ga_make();

    for (int pair = blockIdx.x*NWARP + warp; pair < pairsTotal; pair += gwarps){
        const int p0 = pair * 2;

        __syncwarp();
        // stage x interleaved: xs[i*36 + j*2 + p]
        {
            const float4* s0 = (const float4*)(mv + (size_t)p0 * 512);
            const float4* s1 = s0 + 128;
            #pragma unroll
            for (int k = 0; k < 4; ++k){
                int q = lane + 32*k;
                float4 a = s0[q], b = s1[q];
                int i = q >> 2, j0 = (q & 3) * 4;
                float* dst = xs + i*36 + j0*2;
                *(u64*)(dst + 0) = pk2(a.x, b.x);
                *(u64*)(dst + 2) = pk2(a.y, b.y);
                *(u64*)(dst + 4) = pk2(a.z, b.z);
                *(u64*)(dst + 6) = pk2(a.w, b.w);
            }
            int p = lane >> 4, q = lane & 15;
            float4 v = ((const float4*)(sc + (size_t)(p0 + p)*64))[q];
            ss[(q*4 + 0)*2 + p] = v.x;
            ss[(q*4 + 1)*2 + p] = v.y;
            ss[(q*4 + 2)*2 + p] = v.z;
            ss[(q*4 + 3)*2 + p] = v.w;
        }
        __syncwarp();

        // phase 1: paired equi_linears
        u64 acc0[16], acc1[16];
        #pragma unroll
        for (int j = 0; j < 16; ++j){ acc0[j] = 0ull; acc1[j] = 0ull; }

        #pragma unroll 2
        for (int i = 0; i < 32; ++i){
            u64 x2[16];
            {
                const ulonglong2* xr = (const ulonglong2*)(xs + i*36);
                #pragma unroll
                for (int t = 0; t < 8; ++t){ ulonglong2 v = xr[t]; x2[2*t] = v.x; x2[2*t+1] = v.y; }
            }
            uint4 ua = ((const uint4*)(sm + OFF_WA))[i*32 + lane];
            uint4 ub = ((const uint4*)(sm + OFF_WB))[i*32 + lane];
            unsigned int uc = ((const unsigned int*)(sm + OFF_WC))[i*32 + lane];
            float2 w;
            w = h2f(ua.x); apply_b2<0>(w.x, w.y, x2, acc0, acc1);
            w = h2f(ua.y); apply_b2<1>(w.x, w.y, x2, acc0, acc1);
            w = h2f(ua.z); apply_b2<2>(w.x, w.y, x2, acc0, acc1);
            w = h2f(ua.w); apply_b2<3>(w.x, w.y, x2, acc0, acc1);
            w = h2f(ub.x); apply_b2<4>(w.x, w.y, x2, acc0, acc1);
            w = h2f(ub.y); apply_b2<5>(w.x, w.y, x2, acc0, acc1);
            w = h2f(ub.z); apply_b2<6>(w.x, w.y, x2, acc0, acc1);
            w = h2f(ub.w); apply_b2<7>(w.x, w.y, x2, acc0, acc1);
            w = h2f(uc);   apply_b2<8>(w.x, w.y, x2, acc0, acc1);
        }
        // scalar contribution -> component 0
        #pragma unroll 4
        for (int s2i = 0; s2i < 32; ++s2i){
            uint2 u = ((const uint2*)(sm + OFF_WS))[s2i*32 + lane];
            float2 w01 = h2f(u.x);
            float2 w23 = h2f(u.y);
            ulonglong2 sv = *(const ulonglong2*)(ss + s2i*4);
            acc0[0] = fma2(dup2(w01.x), sv.x, acc0[0]);
            acc1[0] = fma2(dup2(w01.y), sv.x, acc1[0]);
            acc0[0] = fma2(dup2(w23.x), sv.y, acc0[0]);
            acc1[0] = fma2(dup2(w23.y), sv.y, acc1[0]);
        }

        // bilinears (both operands local)
        u64 h2v[16];
        #pragma unroll
        for (int j = 0; j < 16; ++j) h2v[j] = 0ull;

        if (lane < 16){
            #pragma unroll
            for (int j = 0; j < 16; ++j)
                #pragma unroll
                for (int k = 0; k < 16; ++k)
                    if (T.gs[j][k] != 0){
                        u64 a = (T.gs[j][k] > 0) ? acc0[j] : neg2(acc0[j]);
                        h2v[T.gi[j][k]] = fma2(a, acc1[k], h2v[T.gi[j][k]]);
                    }
        } else {
            u64 lam2 = pk2(refmv[(size_t)p0*16 + 15], refmv[(size_t)(p0+1)*16 + 15]);
            #pragma unroll
            for (int j = 0; j < 16; ++j)
                #pragma unroll
                for (int k = 0; k < 16; ++k)
                    if (T.js[j][k] != 0){
                        u64 a = (T.js[j][k] > 0) ? acc0[j] : neg2(acc0[j]);
                        h2v[T.ja[j][k]] = fma2(a, acc1[k], h2v[T.ja[j][k]]);
                    }
            #pragma unroll
            for (int j = 0; j < 16; ++j) h2v[j] = mul2(h2v[j], lam2);
        }

        __syncwarp();
        {
            ulonglong2* hr = (ulonglong2*)(xs + lane*36);
            #pragma unroll
            for (int p = 0; p < 8; ++p) hr[p] = make_ulonglong2(h2v[2*p], h2v[2*p+1]);
        }
        __syncwarp();

        // phase 2: output equi_linear (o = lane) + folded out_s h-reduction
        u64 ao[16];
        #pragma unroll
        for (int j = 0; j < 16; ++j) ao[j] = 0ull;
        u64 as0 = 0ull, as1 = 0ull;

        #pragma unroll 2
        for (int i = 0; i < 32; ++i){
            u64 x2[16];
            {
                const ulonglong2* xr = (const ulonglong2*)(xs + i*36);
                #pragma unroll
                for (int t = 0; t < 8; ++t){ ulonglong2 v = xr[t]; x2[2*t] = v.x; x2[2*t+1] = v.y; }
            }
            uint4 ga = ((const uint4*)(sm + OFF_OA))[i*32 + lane];
            unsigned int gc = ((const unsigned int*)(sm + OFF_OC))[i*32 + lane];
            float2 g;
            g = h2f(ga.x); apply_b1<0>(g.x, x2, ao); apply_b1<1>(g.y, x2, ao);
            g = h2f(ga.y); apply_b1<2>(g.x, x2, ao); apply_b1<3>(g.y, x2, ao);
            g = h2f(ga.z); apply_b1<4>(g.x, x2, ao); apply_b1<5>(g.y, x2, ao);
            g = h2f(ga.w); apply_b1<6>(g.x, x2, ao); apply_b1<7>(g.y, x2, ao);
            g = h2f(gc);   apply_b1<8>(g.x, x2, ao);
            // out_s h-part: x2[0] = h[i] component-0 pair
            float2 wm = h2f(((const unsigned int*)(sm + OFF_M2))[i*32 + lane]);
            as0 = fma2(dup2(wm.x), x2[0], as0);
            as1 = fma2(dup2(wm.y), x2[0], as1);
        }
        // scalars -> component 0
        #pragma unroll 4
        for (int s2i = 0; s2i < 32; ++s2i){
            float2 w = h2f(((const unsigned int*)(sm + OFF_WS2M))[s2i*32 + lane]);
            ulonglong2 sv = *(const ulonglong2*)(ss + s2i*4);
            ao[0] = fma2(dup2(w.x), sv.x, ao[0]);
            ao[0] = fma2(dup2(w.y), sv.y, ao[0]);
        }
        // store out_mv
        {
            float v0[16], v1[16];
            #pragma unroll
            for (int j = 0; j < 16; ++j) unpk2(ao[j], v0[j], v1[j]);
            float* op0 = out + ((size_t)p0*32 + lane)*16;
            float* op1 = op0 + 512;
            #pragma unroll
            for (int j = 0; j < 16; j += 4){
                *(float4*)(op0 + j) = make_float4(v0[j], v0[j+1], v0[j+2], v0[j+3]);
                *(float4*)(op1 + j) = make_float4(v1[j], v1[j+1], v1[j+2], v1[j+3]);
            }
        }

        // out_s scalar part + store
        #pragma unroll 4
        for (int s2i = 0; s2i < 32; ++s2i){
            uint2 u = ((const uint2*)(sm + OFF_WS2S))[s2i*32 + lane];
            float2 w01 = h2f(u.x);
            float2 w23 = h2f(u.y);
            ulonglong2 sv = *(const ulonglong2*)(ss + s2i*4);
            as0 = fma2(dup2(w01.x), sv.x, as0);
            as1 = fma2(dup2(w01.y), sv.x, as1);
            as0 = fma2(dup2(w23.x), sv.y, as0);
            as1 = fma2(dup2(w23.y), sv.y, as1);
        }
        {
            float a0, a1, b0, b1;
            unpk2(as0, a0, a1);
            unpk2(as1, b0, b1);
            outs[(size_t)p0*64 + lane]          = a0;
            outs[(size_t)(p0+1)*64 + lane]      = a1;
            outs[(size_t)p0*64 + 32 + lane]     = b0;
            outs[(size_t)(p0+1)*64 + 32 + lane] = b1;
        }
    }
}

extern "C" void kernel_launch(void* const* d_in, const int* in_sizes, int n_in,
                              void* d_out, int out_size)
{
    const float* mv    = (const float*)d_in[0];
    const float* refmv = (const float*)d_in[1];
    const float* sc    = (const float*)d_in[2];
    const float* wLmv  = (const float*)d_in[6];
    const float* wLs   = (const float*)d_in[7];
    const float* wRmv  = (const float*)d_in[8];
    const float* wRs   = (const float*)d_in[9];
    const float* wJLmv = (const float*)d_in[10];
    const float* wJLs  = (const float*)d_in[11];
    const float* wJRmv = (const float*)d_in[12];
    const float* wJRs  = (const float*)d_in[13];
    const float* wOmv  = (const float*)d_in[14];
    const float* wOs2m = (const float*)d_in[15];
    const float* wM2s  = (const float*)d_in[16];
    const float* wS2s  = (const float*)d_in[17];
    float* out = (float*)d_out;

    const int P = in_sizes[0] / 512;
    const int pairs = P / 2;

    int sms = 148;
    cudaDeviceGetAttribute(&sms, cudaDevAttrMultiProcessorCount, 0);

    const size_t smem = (size_t)SMEMF * sizeof(float);
    cudaFuncSetAttribute(fused_kernel, cudaFuncAttributeMaxDynamicSharedMemorySize, (int)smem);

    fused_kernel<<<sms, NTHR, smem>>>(mv, refmv, sc,
                                      wLmv, wLs, wRmv, wRs,
                                      wJLmv, wJLs, wJRmv, wJRs,
                                      wOmv, wOs2m, wM2s, wS2s,
                                      out, pairs, P);
}

// round 13
// speedup vs baseline: 1.3293x; 1.0231x over previous
#include <cuda_runtime.h>
#include <cuda_fp16.h>

#define NWARP 16
#define NTHR  (NWARP*32)
typedef unsigned long long u64;

__host__ __device__ constexpr int ga_popc(int x){ return (x&1)+((x>>1)&1)+((x>>2)&1)+((x>>3)&1); }
__host__ __device__ constexpr int ga_mask(int i){
    return i==0?0: i==1?1: i==2?2: i==3?4: i==4?8: i==5?3: i==6?5: i==7?9:
           i==8?6: i==9?10: i==10?12: i==11?7: i==12?11: i==13?13: i==14?14: 15;
}
__host__ __device__ constexpr int ga_idx(int m){
    return m==0?0: m==1?1: m==2?2: m==4?3: m==8?4: m==3?5: m==5?6: m==9?7:
           m==6?8: m==10?9: m==12?10: m==7?11: m==11?12: m==13?13: m==14?14: 15;
}
__host__ __device__ constexpr int ga_grade(int i){ return ga_popc(ga_mask(i)); }
__host__ __device__ constexpr int ga_csign(int a, int b){
    int s = 0;
    for (int i = 0; i < 4; ++i) if ((b>>i)&1) s += ga_popc(a >> (i+1));
    return (s&1) ? -1 : 1;
}
__host__ __device__ constexpr int ga_dsign(int b){ return ga_csign(ga_mask(b), 15 ^ ga_mask(b)); }

struct GaTabs { signed char gs[16][16], gi[16][16], js[16][16], ja[16][16]; };
__host__ __device__ constexpr GaTabs ga_make(){
    GaTabs t{};
    for (int j = 0; j < 16; ++j)
        for (int k = 0; k < 16; ++k){
            int mj = ga_mask(j), mk = ga_mask(k);
            if (mj & mk & 1){ t.gs[j][k]=0; t.gi[j][k]=0; }
            else { t.gs[j][k]=(signed char)ga_csign(mj,mk); t.gi[j][k]=(signed char)ga_idx(mj^mk); }
            int jm = 15^mj, km = 15^mk;
            if (jm & km){ t.js[j][k]=0; t.ja[j][k]=0; }
            else {
                int im = jm^km;
                int s = ga_csign(im,15^im)*ga_csign(jm,km)*ga_dsign(j)*ga_dsign(k);
                t.js[j][k]=(signed char)s; t.ja[j][k]=(signed char)ga_idx(15^im);
            }
        }
    return t;
}

__device__ __forceinline__ u64 pk2(float a, float b){ u64 r; asm("mov.b64 %0,{%1,%2};":"=l"(r):"f"(a),"f"(b)); return r; }
__device__ __forceinline__ void unpk2(u64 v, float& a, float& b){ asm("mov.b64 {%0,%1},%2;":"=f"(a),"=f"(b):"l"(v)); }
__device__ __forceinline__ u64 dup2(float a){ u64 r; asm("mov.b64 %0,{%1,%1};":"=l"(r):"f"(a)); return r; }
__device__ __forceinline__ u64 fma2(u64 a, u64 b, u64 c){ u64 d; asm("fma.rn.f32x2 %0,%1,%2,%3;":"=l"(d):"l"(a),"l"(b),"l"(c)); return d; }
__device__ __forceinline__ u64 mul2(u64 a, u64 b){ u64 d; asm("mul.rn.f32x2 %0,%1,%2;":"=l"(d):"l"(a),"l"(b)); return d; }
__device__ __forceinline__ u64 neg2(u64 a){ return a ^ 0x8000000080000000ull; }
__device__ __forceinline__ float2 h2f(unsigned int u){ __half2 h = *(__half2*)&u; return __half22float2(h); }

template<int B>
__device__ __forceinline__ void apply_b2(float wa, float wb, const u64* x2, u64* a0, u64* a1){
    u64 w0 = dup2(wa), w1 = dup2(wb);
    #pragma unroll
    for (int j = 0; j < 16; ++j){
        if (B < 5){
            if (ga_grade(j) == B){ a0[j]=fma2(w0,x2[j],a0[j]); a1[j]=fma2(w1,x2[j],a1[j]); }
        } else {
            if (!(ga_mask(j)&1) && ga_grade(j) == B-5){
                const int jj = ga_idx(ga_mask(j)|1);
                a0[jj]=fma2(w0,x2[j],a0[jj]); a1[jj]=fma2(w1,x2[j],a1[jj]);
            }
        }
    }
}
template<int B>
__device__ __forceinline__ void apply_b1(float wv, const u64* x2, u64* a){
    u64 w = dup2(wv);
    #pragma unroll
    for (int j = 0; j < 16; ++j){
        if (B < 5){
            if (ga_grade(j) == B) a[j] = fma2(w, x2[j], a[j]);
        } else {
            if (!(ga_mask(j)&1) && ga_grade(j) == B-5){
                const int jj = ga_idx(ga_mask(j)|1);
                a[jj] = fma2(w, x2[j], a[jj]);
            }
        }
    }
}

// smem layout (float units)
#define OFF_WA    0
#define OFF_WB    4096
#define OFF_WC    8192
#define OFF_WS    9216
#define OFF_OA    11264
#define OFF_OC    15360
#define OFF_WS2M  16384
#define OFF_M2    17408
#define OFF_WS2S  18432
#define OFF_STG   20480
#define STGW      1280
#define SMEMF     (OFF_STG + NWARP*STGW)   /* 40960 fl = 163.8 KB */

__global__ void __launch_bounds__(NTHR, 1)
fused_kernel(const float* __restrict__ mv, const float* __restrict__ refmv,
             const float* __restrict__ sc,
             const float* __restrict__ wLmv, const float* __restrict__ wLs,
             const float* __restrict__ wRmv, const float* __restrict__ wRs,
             const float* __restrict__ wJLmv, const float* __restrict__ wJLs,
             const float* __restrict__ wJRmv, const float* __restrict__ wJRs,
             const float* __restrict__ wOmv,  const float* __restrict__ wOs2mv,
             const float* __restrict__ wM2s,  const float* __restrict__ wS2s,
             float* __restrict__ out, int pairsTotal, int P)
{
    extern __shared__ float sm[];
    const int tid = threadIdx.x, warp = tid>>5, lane = tid&31;

    // ---- weight repacks (fp32 -> fp16) ----
    {
        __half2* WA = (__half2*)(sm + OFF_WA);
        __half2* WB = (__half2*)(sm + OFF_WB);
        __half2* WC = (__half2*)(sm + OFF_WC);
        for (int idx = tid; idx < 1024; idx += NTHR){
            int i = idx >> 5, l = idx & 31, o = l & 15;
            const float* A = (l < 16) ? wLmv : wJLmv;
            const float* B = (l < 16) ? wRmv : wJRmv;
            int base = (o*32+i)*9;
            #pragma unroll
            for (int b = 0; b < 4; ++b){
                WA[idx*4 + b] = __floats2half2_rn(A[base+b],   B[base+b]);
                WB[idx*4 + b] = __floats2half2_rn(A[base+4+b], B[base+4+b]);
            }
            WC[idx] = __floats2half2_rn(A[base+8], B[base+8]);
        }
        __half2* WSX = (__half2*)(sm + OFF_WS);
        for (int idx = tid; idx < 2048; idx += NTHR){
            int se = idx & 1, l = (idx>>1) & 31, s2 = idx >> 6, o = l & 15;
            const float* T0 = (l<16) ? wLs : wJLs;
            const float* T1 = (l<16) ? wRs : wJRs;
            WSX[idx] = __floats2half2_rn(T0[o*64 + s2*2 + se], T1[o*64 + s2*2 + se]);
        }
        __half2* OA = (__half2*)(sm + OFF_OA);
        __half2* OC = (__half2*)(sm + OFF_OC);
        for (int idx = tid; idx < 1024; idx += NTHR){
            int i = idx >> 5, l = idx & 31;
            int base = (l*32+i)*9;
            #pragma unroll
            for (int q = 0; q < 4; ++q)
                OA[idx*4 + q] = __floats2half2_rn(wOmv[base+2*q], wOmv[base+2*q+1]);
            OC[idx] = __floats2half2_rn(wOmv[base+8], 0.f);
        }
        __half2* WS2 = (__half2*)(sm + OFF_WS2M);
        for (int idx = tid; idx < 1024; idx += NTHR){
            int l = idx & 31, s2 = idx >> 5;
            WS2[idx] = __floats2half2_rn(wOs2mv[l*64 + s2*2], wOs2mv[l*64 + s2*2 + 1]);
        }
        __half2* M2 = (__half2*)(sm + OFF_M2);
        for (int idx = tid; idx < 1024; idx += NTHR){
            int i = idx >> 5, l = idx & 31;
            M2[idx] = __floats2half2_rn(wM2s[l*32 + i], wM2s[(l+32)*32 + i]);
        }
        __half2* WSS = (__half2*)(sm + OFF_WS2S);
        for (int idx = tid; idx < 2048; idx += NTHR){
            int k = idx & 1, l = (idx>>1) & 31, s2 = idx >> 6;
            WSS[idx] = __floats2half2_rn(wS2s[l*64 + s2*2 + k], wS2s[(l+32)*64 + s2*2 + k]);
        }
    }
    __syncthreads();

    float* xs = sm + OFF_STG + warp * STGW;   // [32][36] x/h + [64][2] scalars
    float* ss = xs + 1152;
    float* outs = out + (size_t)P * 512;
    const int gwarps = gridDim.x * NWARP;
    constexpr GaTabs T = ga_make();

    for (int pair = blockIdx.x*NWARP + warp; pair < pairsTotal; pair += gwarps){
        const int p0 = pair * 2;

        __syncwarp();
        // stage x interleaved: xs[i*36 + j*2 + p]
        {
            const float4* s0 = (const float4*)(mv + (size_t)p0 * 512);
            const float4* s1 = s0 + 128;
            #pragma unroll
            for (int k = 0; k < 4; ++k){
                int q = lane + 32*k;
                float4 a = s0[q], b = s1[q];
                int i = q >> 2, j0 = (q & 3) * 4;
                float* dst = xs + i*36 + j0*2;
                *(ulonglong2*)(dst    ) = make_ulonglong2(pk2(a.x, b.x), pk2(a.y, b.y));
                *(ulonglong2*)(dst + 4) = make_ulonglong2(pk2(a.z, b.z), pk2(a.w, b.w));
            }
            int p = lane >> 4, q = lane & 15;
            float4 v = ((const float4*)(sc + (size_t)(p0 + p)*64))[q];
            ss[(q*4 + 0)*2 + p] = v.x;
            ss[(q*4 + 1)*2 + p] = v.y;
            ss[(q*4 + 2)*2 + p] = v.z;
            ss[(q*4 + 3)*2 + p] = v.w;
        }
        __syncwarp();

        // phase 1: paired equi_linears
        u64 acc0[16], acc1[16];
        #pragma unroll
        for (int j = 0; j < 16; ++j){ acc0[j] = 0ull; acc1[j] = 0ull; }

        #pragma unroll 4
        for (int i = 0; i < 32; ++i){
            u64 x2[16];
            {
                const ulonglong2* xr = (const ulonglong2*)(xs + i*36);
                #pragma unroll
                for (int t = 0; t < 8; ++t){ ulonglong2 v = xr[t]; x2[2*t] = v.x; x2[2*t+1] = v.y; }
            }
            uint4 ua = ((const uint4*)(sm + OFF_WA))[i*32 + lane];
            uint4 ub = ((const uint4*)(sm + OFF_WB))[i*32 + lane];
            unsigned int uc = ((const unsigned int*)(sm + OFF_WC))[i*32 + lane];
            float2 w;
            w = h2f(ua.x); apply_b2<0>(w.x, w.y, x2, acc0, acc1);
            w = h2f(ua.y); apply_b2<1>(w.x, w.y, x2, acc0, acc1);
            w = h2f(ua.z); apply_b2<2>(w.x, w.y, x2, acc0, acc1);
            w = h2f(ua.w); apply_b2<3>(w.x, w.y, x2, acc0, acc1);
            w = h2f(ub.x); apply_b2<4>(w.x, w.y, x2, acc0, acc1);
            w = h2f(ub.y); apply_b2<5>(w.x, w.y, x2, acc0, acc1);
            w = h2f(ub.z); apply_b2<6>(w.x, w.y, x2, acc0, acc1);
            w = h2f(ub.w); apply_b2<7>(w.x, w.y, x2, acc0, acc1);
            w = h2f(uc);   apply_b2<8>(w.x, w.y, x2, acc0, acc1);
        }
        // scalar contribution -> component 0
        #pragma unroll 4
        for (int s2i = 0; s2i < 32; ++s2i){
            uint2 u = ((const uint2*)(sm + OFF_WS))[s2i*32 + lane];
            float2 w01 = h2f(u.x);
            float2 w23 = h2f(u.y);
            ulonglong2 sv = *(const ulonglong2*)(ss + s2i*4);
            acc0[0] = fma2(dup2(w01.x), sv.x, acc0[0]);
            acc1[0] = fma2(dup2(w01.y), sv.x, acc1[0]);
            acc0[0] = fma2(dup2(w23.x), sv.y, acc0[0]);
            acc1[0] = fma2(dup2(w23.y), sv.y, acc1[0]);
        }

        // bilinears (both operands local)
        u64 h2v[16];
        #pragma unroll
        for (int j = 0; j < 16; ++j) h2v[j] = 0ull;

        if (lane < 16){
            #pragma unroll
            for (int j = 0; j < 16; ++j)
                #pragma unroll
                for (int k = 0; k < 16; ++k)
                    if (T.gs[j][k] != 0){
                        u64 a = (T.gs[j][k] > 0) ? acc0[j] : neg2(acc0[j]);
                        h2v[T.gi[j][k]] = fma2(a, acc1[k], h2v[T.gi[j][k]]);
                    }
        } else {
            u64 lam2 = pk2(refmv[(size_t)p0*16 + 15], refmv[(size_t)(p0+1)*16 + 15]);
            #pragma unroll
            for (int j = 0; j < 16; ++j)
                #pragma unroll
                for (int k = 0; k < 16; ++k)
                    if (T.js[j][k] != 0){
                        u64 a = (T.js[j][k] > 0) ? acc0[j] : neg2(acc0[j]);
                        h2v[T.ja[j][k]] = fma2(a, acc1[k], h2v[T.ja[j][k]]);
                    }
            #pragma unroll
            for (int j = 0; j < 16; ++j) h2v[j] = mul2(h2v[j], lam2);
        }

        __syncwarp();
        {
            ulonglong2* hr = (ulonglong2*)(xs + lane*36);
            #pragma unroll
            for (int p = 0; p < 8; ++p) hr[p] = make_ulonglong2(h2v[2*p], h2v[2*p+1]);
        }
        __syncwarp();

        // phase 2: output equi_linear (o = lane) + folded out_s h-reduction
        u64 ao[16];
        #pragma unroll
        for (int j = 0; j < 16; ++j) ao[j] = 0ull;
        u64 as0 = 0ull, as1 = 0ull;

        #pragma unroll 4
        for (int i = 0; i < 32; ++i){
            u64 x2[16];
            {
                const ulonglong2* xr = (const ulonglong2*)(xs + i*36);
                #pragma unroll
                for (int t = 0; t < 8; ++t){ ulonglong2 v = xr[t]; x2[2*t] = v.x; x2[2*t+1] = v.y; }
            }
            uint4 ga = ((const uint4*)(sm + OFF_OA))[i*32 + lane];
            unsigned int gc = ((const unsigned int*)(sm + OFF_OC))[i*32 + lane];
            float2 g;
            g = h2f(ga.x); apply_b1<0>(g.x, x2, ao); apply_b1<1>(g.y, x2, ao);
            g = h2f(ga.y); apply_b1<2>(g.x, x2, ao); apply_b1<3>(g.y, x2, ao);
            g = h2f(ga.z); apply_b1<4>(g.x, x2, ao); apply_b1<5>(g.y, x2, ao);
            g = h2f(ga.w); apply_b1<6>(g.x, x2, ao); apply_b1<7>(g.y, x2, ao);
            g = h2f(gc);   apply_b1<8>(g.x, x2, ao);
            // out_s h-part: x2[0] = h[i] component-0 pair
            float2 wm = h2f(((const unsigned int*)(sm + OFF_M2))[i*32 + lane]);
            as0 = fma2(dup2(wm.x), x2[0], as0);
            as1 = fma2(dup2(wm.y), x2[0], as1);
        }

        // fused scalar loops: out_mv comp-0 (WS2M) + out_s scalar part (WS2S), one sv read
        #pragma unroll 4
        for (int s2i = 0; s2i < 32; ++s2i){
            ulonglong2 sv = *(const ulonglong2*)(ss + s2i*4);
            float2 wm2 = h2f(((const unsigned int*)(sm + OFF_WS2M))[s2i*32 + lane]);
            ao[0] = fma2(dup2(wm2.x), sv.x, ao[0]);
            ao[0] = fma2(dup2(wm2.y), sv.y, ao[0]);
            uint2 u = ((const uint2*)(sm + OFF_WS2S))[s2i*32 + lane];
            float2 w01 = h2f(u.x);
            float2 w23 = h2f(u.y);
            as0 = fma2(dup2(w01.x), sv.x, as0);
            as1 = fma2(dup2(w01.y), sv.x, as1);
            as0 = fma2(dup2(w23.x), sv.y, as0);
            as1 = fma2(dup2(w23.y), sv.y, as1);
        }

        // store out_mv
        {
            float v0[16], v1[16];
            #pragma unroll
            for (int j = 0; j < 16; ++j) unpk2(ao[j], v0[j], v1[j]);
            float* op0 = out + ((size_t)p0*32 + lane)*16;
            float* op1 = op0 + 512;
            #pragma unroll
            for (int j = 0; j < 16; j += 4){
                *(float4*)(op0 + j) = make_float4(v0[j], v0[j+1], v0[j+2], v0[j+3]);
                *(float4*)(op1 + j) = make_float4(v1[j], v1[j+1], v1[j+2], v1[j+3]);
            }
        }
        // store out_s
        {
            float a0, a1, b0, b1;
            unpk2(as0, a0, a1);
            unpk2(as1, b0, b1);
            outs[(size_t)p0*64 + lane]          = a0;
            outs[(size_t)(p0+1)*64 + lane]      = a1;
            outs[(size_t)p0*64 + 32 + lane]     = b0;
            outs[(size_t)(p0+1)*64 + 32 + lane] = b1;
        }
    }
}

extern "C" void kernel_launch(void* const* d_in, const int* in_sizes, int n_in,
                              void* d_out, int out_size)
{
    const float* mv    = (const float*)d_in[0];
    const float* refmv = (const float*)d_in[1];
    const float* sc    = (const float*)d_in[2];
    const float* wLmv  = (const float*)d_in[6];
    const float* wLs   = (const float*)d_in[7];
    const float* wRmv  = (const float*)d_in[8];
    const float* wRs   = (const float*)d_in[9];
    const float* wJLmv = (const float*)d_in[10];
    const float* wJLs  = (const float*)d_in[11];
    const float* wJRmv = (const float*)d_in[12];
    const float* wJRs  = (const float*)d_in[13];
    const float* wOmv  = (const float*)d_in[14];
    const float* wOs2m = (const float*)d_in[15];
    const float* wM2s  = (const float*)d_in[16];
    const float* wS2s  = (const float*)d_in[17];
    float* out = (float*)d_out;

    const int P = in_sizes[0] / 512;
    const int pairs = P / 2;

    int sms = 148;
    cudaDeviceGetAttribute(&sms, cudaDevAttrMultiProcessorCount, 0);

    const size_t smem = (size_t)SMEMF * sizeof(float);
    cudaFuncSetAttribute(fused_kernel, cudaFuncAttributeMaxDynamicSharedMemorySize, (int)smem);

    fused_kernel<<<sms, NTHR, smem>>>(mv, refmv, sc,
                                      wLmv, wLs, wRmv, wRs,
                                      wJLmv, wJLs, wJRmv, wJRs,
                                      wOmv, wOs2m, wM2s, wS2s,
                                      out, pairs, P);
}

// round 14
// speedup vs baseline: 1.3434x; 1.0106x over previous
#include <cuda_runtime.h>
#include <cuda_fp16.h>

#define NWARP 16
#define NTHR  (NWARP*32)
typedef unsigned long long u64;

__host__ __device__ constexpr int ga_popc(int x){ return (x&1)+((x>>1)&1)+((x>>2)&1)+((x>>3)&1); }
__host__ __device__ constexpr int ga_mask(int i){
    return i==0?0: i==1?1: i==2?2: i==3?4: i==4?8: i==5?3: i==6?5: i==7?9:
           i==8?6: i==9?10: i==10?12: i==11?7: i==12?11: i==13?13: i==14?14: 15;
}
__host__ __device__ constexpr int ga_idx(int m){
    return m==0?0: m==1?1: m==2?2: m==4?3: m==8?4: m==3?5: m==5?6: m==9?7:
           m==6?8: m==10?9: m==12?10: m==7?11: m==11?12: m==13?13: m==14?14: 15;
}
__host__ __device__ constexpr int ga_grade(int i){ return ga_popc(ga_mask(i)); }
__host__ __device__ constexpr int ga_csign(int a, int b){
    int s = 0;
    for (int i = 0; i < 4; ++i) if ((b>>i)&1) s += ga_popc(a >> (i+1));
    return (s&1) ? -1 : 1;
}
__host__ __device__ constexpr int ga_dsign(int b){ return ga_csign(ga_mask(b), 15 ^ ga_mask(b)); }

struct GaTabs { signed char gs[16][16], gi[16][16], js[16][16], ja[16][16]; };
__host__ __device__ constexpr GaTabs ga_make(){
    GaTabs t{};
    for (int j = 0; j < 16; ++j)
        for (int k = 0; k < 16; ++k){
            int mj = ga_mask(j), mk = ga_mask(k);
            if (mj & mk & 1){ t.gs[j][k]=0; t.gi[j][k]=0; }
            else { t.gs[j][k]=(signed char)ga_csign(mj,mk); t.gi[j][k]=(signed char)ga_idx(mj^mk); }
            int jm = 15^mj, km = 15^mk;
            if (jm & km){ t.js[j][k]=0; t.ja[j][k]=0; }
            else {
                int im = jm^km;
                int s = ga_csign(im,15^im)*ga_csign(jm,km)*ga_dsign(j)*ga_dsign(k);
                t.js[j][k]=(signed char)s; t.ja[j][k]=(signed char)ga_idx(15^im);
            }
        }
    return t;
}

__device__ __forceinline__ u64 pk2(float a, float b){ u64 r; asm("mov.b64 %0,{%1,%2};":"=l"(r):"f"(a),"f"(b)); return r; }
__device__ __forceinline__ void unpk2(u64 v, float& a, float& b){ asm("mov.b64 {%0,%1},%2;":"=f"(a),"=f"(b):"l"(v)); }
__device__ __forceinline__ u64 dup2(float a){ u64 r; asm("mov.b64 %0,{%1,%1};":"=l"(r):"f"(a)); return r; }
__device__ __forceinline__ u64 fma2(u64 a, u64 b, u64 c){ u64 d; asm("fma.rn.f32x2 %0,%1,%2,%3;":"=l"(d):"l"(a),"l"(b),"l"(c)); return d; }
__device__ __forceinline__ u64 mul2(u64 a, u64 b){ u64 d; asm("mul.rn.f32x2 %0,%1,%2;":"=l"(d):"l"(a),"l"(b)); return d; }
__device__ __forceinline__ u64 neg2(u64 a){ return a ^ 0x8000000080000000ull; }
__device__ __forceinline__ float2 h2f(unsigned int u){ __half2 h = *(__half2*)&u; return __half22float2(h); }
__device__ __forceinline__ void pf_l2(const void* p){ asm volatile("prefetch.global.L2 [%0];" :: "l"(p)); }

template<int B>
__device__ __forceinline__ void apply_b2(float wa, float wb, const u64* x2, u64* a0, u64* a1){
    u64 w0 = dup2(wa), w1 = dup2(wb);
    #pragma unroll
    for (int j = 0; j < 16; ++j){
        if (B < 5){
            if (ga_grade(j) == B){ a0[j]=fma2(w0,x2[j],a0[j]); a1[j]=fma2(w1,x2[j],a1[j]); }
        } else {
            if (!(ga_mask(j)&1) && ga_grade(j) == B-5){
                const int jj = ga_idx(ga_mask(j)|1);
                a0[jj]=fma2(w0,x2[j],a0[jj]); a1[jj]=fma2(w1,x2[j],a1[jj]);
            }
        }
    }
}
template<int B>
__device__ __forceinline__ void apply_b1(float wv, const u64* x2, u64* a){
    u64 w = dup2(wv);
    #pragma unroll
    for (int j = 0; j < 16; ++j){
        if (B < 5){
            if (ga_grade(j) == B) a[j] = fma2(w, x2[j], a[j]);
        } else {
            if (!(ga_mask(j)&1) && ga_grade(j) == B-5){
                const int jj = ga_idx(ga_mask(j)|1);
                a[jj] = fma2(w, x2[j], a[jj]);
            }
        }
    }
}

// smem layout (float units)
#define OFF_WA    0
#define OFF_WB    4096
#define OFF_WC    8192
#define OFF_WS    9216
#define OFF_OA    11264
#define OFF_OC    15360
#define OFF_WS2M  16384
#define OFF_M2    17408
#define OFF_WS2S  18432
#define OFF_STG   20480
#define STGW      1280
#define SMEMF     (OFF_STG + NWARP*STGW)   /* 40960 fl = 163.8 KB */

__global__ void __launch_bounds__(NTHR, 1)
fused_kernel(const float* __restrict__ mv, const float* __restrict__ refmv,
             const float* __restrict__ sc,
             const float* __restrict__ wLmv, const float* __restrict__ wLs,
             const float* __restrict__ wRmv, const float* __restrict__ wRs,
             const float* __restrict__ wJLmv, const float* __restrict__ wJLs,
             const float* __restrict__ wJRmv, const float* __restrict__ wJRs,
             const float* __restrict__ wOmv,  const float* __restrict__ wOs2mv,
             const float* __restrict__ wM2s,  const float* __restrict__ wS2s,
             float* __restrict__ out, int pairsTotal, int P)
{
    extern __shared__ float sm[];
    const int tid = threadIdx.x, warp = tid>>5, lane = tid&31;

    // ---- weight repacks (fp32 -> fp16) ----
    {
        __half2* WA = (__half2*)(sm + OFF_WA);
        __half2* WB = (__half2*)(sm + OFF_WB);
        __half2* WC = (__half2*)(sm + OFF_WC);
        for (int idx = tid; idx < 1024; idx += NTHR){
            int i = idx >> 5, l = idx & 31, o = l & 15;
            const float* A = (l < 16) ? wLmv : wJLmv;
            const float* B = (l < 16) ? wRmv : wJRmv;
            int base = (o*32+i)*9;
            #pragma unroll
            for (int b = 0; b < 4; ++b){
                WA[idx*4 + b] = __floats2half2_rn(A[base+b],   B[base+b]);
                WB[idx*4 + b] = __floats2half2_rn(A[base+4+b], B[base+4+b]);
            }
            WC[idx] = __floats2half2_rn(A[base+8], B[base+8]);
        }
        __half2* WSX = (__half2*)(sm + OFF_WS);
        for (int idx = tid; idx < 2048; idx += NTHR){
            int se = idx & 1, l = (idx>>1) & 31, s2 = idx >> 6, o = l & 15;
            const float* T0 = (l<16) ? wLs : wJLs;
            const float* T1 = (l<16) ? wRs : wJRs;
            WSX[idx] = __floats2half2_rn(T0[o*64 + s2*2 + se], T1[o*64 + s2*2 + se]);
        }
        __half2* OA = (__half2*)(sm + OFF_OA);
        __half2* OC = (__half2*)(sm + OFF_OC);
        for (int idx = tid; idx < 1024; idx += NTHR){
            int i = idx >> 5, l = idx & 31;
            int base = (l*32+i)*9;
            #pragma unroll
            for (int q = 0; q < 4; ++q)
                OA[idx*4 + q] = __floats2half2_rn(wOmv[base+2*q], wOmv[base+2*q+1]);
            OC[idx] = __floats2half2_rn(wOmv[base+8], 0.f);
        }
        __half2* WS2 = (__half2*)(sm + OFF_WS2M);
        for (int idx = tid; idx < 1024; idx += NTHR){
            int l = idx & 31, s2 = idx >> 5;
            WS2[idx] = __floats2half2_rn(wOs2mv[l*64 + s2*2], wOs2mv[l*64 + s2*2 + 1]);
        }
        __half2* M2 = (__half2*)(sm + OFF_M2);
        for (int idx = tid; idx < 1024; idx += NTHR){
            int i = idx >> 5, l = idx & 31;
            M2[idx] = __floats2half2_rn(wM2s[l*32 + i], wM2s[(l+32)*32 + i]);
        }
        __half2* WSS = (__half2*)(sm + OFF_WS2S);
        for (int idx = tid; idx < 2048; idx += NTHR){
            int k = idx & 1, l = (idx>>1) & 31, s2 = idx >> 6;
            WSS[idx] = __floats2half2_rn(wS2s[l*64 + s2*2 + k], wS2s[(l+32)*64 + s2*2 + k]);
        }
    }
    __syncthreads();

    float* xs = sm + OFF_STG + warp * STGW;   // [32][36] x/h + [64][2] scalars
    float* ss = xs + 1152;
    float* outs = out + (size_t)P * 512;
    const int gwarps = gridDim.x * NWARP;
    constexpr GaTabs T = ga_make();

    for (int pair = blockIdx.x*NWARP + warp; pair < pairsTotal; pair += gwarps){
        const int p0 = pair * 2;

        __syncwarp();
        // stage x interleaved: xs[i*36 + j*2 + p]
        {
            const float4* s0 = (const float4*)(mv + (size_t)p0 * 512);
            const float4* s1 = s0 + 128;
            #pragma unroll
            for (int k = 0; k < 4; ++k){
                int q = lane + 32*k;
                float4 a = s0[q], b = s1[q];
                int i = q >> 2, j0 = (q & 3) * 4;
                float* dst = xs + i*36 + j0*2;
                *(ulonglong2*)(dst    ) = make_ulonglong2(pk2(a.x, b.x), pk2(a.y, b.y));
                *(ulonglong2*)(dst + 4) = make_ulonglong2(pk2(a.z, b.z), pk2(a.w, b.w));
            }
            int p = lane >> 4, q = lane & 15;
            float4 v = ((const float4*)(sc + (size_t)(p0 + p)*64))[q];
            ss[(q*4 + 0)*2 + p] = v.x;
            ss[(q*4 + 1)*2 + p] = v.y;
            ss[(q*4 + 2)*2 + p] = v.z;
            ss[(q*4 + 3)*2 + p] = v.w;
        }
        __syncwarp();

        // prefetch next pair's inputs into L2 while this pair computes
        {
            int nxt = pair + gwarps;
            if (nxt < pairsTotal){
                const size_t np0 = (size_t)nxt * 2;
                pf_l2(mv + np0*512 + (size_t)lane*32);            // 32 lines = 4KB mv
                if (lane < 4)  pf_l2(sc + np0*64 + (size_t)lane*32);  // 512B scalars
                if (lane == 4) pf_l2(refmv + np0*16 + 15);
            }
        }

        // phase 1: paired equi_linears
        u64 acc0[16], acc1[16];
        #pragma unroll
        for (int j = 0; j < 16; ++j){ acc0[j] = 0ull; acc1[j] = 0ull; }

        #pragma unroll 8
        for (int i = 0; i < 32; ++i){
            u64 x2[16];
            {
                const ulonglong2* xr = (const ulonglong2*)(xs + i*36);
                #pragma unroll
                for (int t = 0; t < 8; ++t){ ulonglong2 v = xr[t]; x2[2*t] = v.x; x2[2*t+1] = v.y; }
            }
            uint4 ua = ((const uint4*)(sm + OFF_WA))[i*32 + lane];
            uint4 ub = ((const uint4*)(sm + OFF_WB))[i*32 + lane];
            unsigned int uc = ((const unsigned int*)(sm + OFF_WC))[i*32 + lane];
            float2 w;
            w = h2f(ua.x); apply_b2<0>(w.x, w.y, x2, acc0, acc1);
            w = h2f(ua.y); apply_b2<1>(w.x, w.y, x2, acc0, acc1);
            w = h2f(ua.z); apply_b2<2>(w.x, w.y, x2, acc0, acc1);
            w = h2f(ua.w); apply_b2<3>(w.x, w.y, x2, acc0, acc1);
            w = h2f(ub.x); apply_b2<4>(w.x, w.y, x2, acc0, acc1);
            w = h2f(ub.y); apply_b2<5>(w.x, w.y, x2, acc0, acc1);
            w = h2f(ub.z); apply_b2<6>(w.x, w.y, x2, acc0, acc1);
            w = h2f(ub.w); apply_b2<7>(w.x, w.y, x2, acc0, acc1);
            w = h2f(uc);   apply_b2<8>(w.x, w.y, x2, acc0, acc1);
        }
        // scalar contribution -> component 0
        #pragma unroll 4
        for (int s2i = 0; s2i < 32; ++s2i){
            uint2 u = ((const uint2*)(sm + OFF_WS))[s2i*32 + lane];
            float2 w01 = h2f(u.x);
            float2 w23 = h2f(u.y);
            ulonglong2 sv = *(const ulonglong2*)(ss + s2i*4);
            acc0[0] = fma2(dup2(w01.x), sv.x, acc0[0]);
            acc1[0] = fma2(dup2(w01.y), sv.x, acc1[0]);
            acc0[0] = fma2(dup2(w23.x), sv.y, acc0[0]);
            acc1[0] = fma2(dup2(w23.y), sv.y, acc1[0]);
        }

        // bilinears (both operands local)
        u64 h2v[16];
        #pragma unroll
        for (int j = 0; j < 16; ++j) h2v[j] = 0ull;

        if (lane < 16){
            #pragma unroll
            for (int j = 0; j < 16; ++j)
                #pragma unroll
                for (int k = 0; k < 16; ++k)
                    if (T.gs[j][k] != 0){
                        u64 a = (T.gs[j][k] > 0) ? acc0[j] : neg2(acc0[j]);
                        h2v[T.gi[j][k]] = fma2(a, acc1[k], h2v[T.gi[j][k]]);
                    }
        } else {
            u64 lam2 = pk2(refmv[(size_t)p0*16 + 15], refmv[(size_t)(p0+1)*16 + 15]);
            #pragma unroll
            for (int j = 0; j < 16; ++j)
                #pragma unroll
                for (int k = 0; k < 16; ++k)
                    if (T.js[j][k] != 0){
                        u64 a = (T.js[j][k] > 0) ? acc0[j] : neg2(acc0[j]);
                        h2v[T.ja[j][k]] = fma2(a, acc1[k], h2v[T.ja[j][k]]);
                    }
            #pragma unroll
            for (int j = 0; j < 16; ++j) h2v[j] = mul2(h2v[j], lam2);
        }

        __syncwarp();
        {
            ulonglong2* hr = (ulonglong2*)(xs + lane*36);
            #pragma unroll
            for (int p = 0; p < 8; ++p) hr[p] = make_ulonglong2(h2v[2*p], h2v[2*p+1]);
        }
        __syncwarp();

        // phase 2: output equi_linear (o = lane) + folded out_s h-reduction
        u64 ao[16];
        #pragma unroll
        for (int j = 0; j < 16; ++j) ao[j] = 0ull;
        u64 as0 = 0ull, as1 = 0ull;

        #pragma unroll 8
        for (int i = 0; i < 32; ++i){
            u64 x2[16];
            {
                const ulonglong2* xr = (const ulonglong2*)(xs + i*36);
                #pragma unroll
                for (int t = 0; t < 8; ++t){ ulonglong2 v = xr[t]; x2[2*t] = v.x; x2[2*t+1] = v.y; }
            }
            uint4 ga = ((const uint4*)(sm + OFF_OA))[i*32 + lane];
            unsigned int gc = ((const unsigned int*)(sm + OFF_OC))[i*32 + lane];
            float2 g;
            g = h2f(ga.x); apply_b1<0>(g.x, x2, ao); apply_b1<1>(g.y, x2, ao);
            g = h2f(ga.y); apply_b1<2>(g.x, x2, ao); apply_b1<3>(g.y, x2, ao);
            g = h2f(ga.z); apply_b1<4>(g.x, x2, ao); apply_b1<5>(g.y, x2, ao);
            g = h2f(ga.w); apply_b1<6>(g.x, x2, ao); apply_b1<7>(g.y, x2, ao);
            g = h2f(gc);   apply_b1<8>(g.x, x2, ao);
            float2 wm = h2f(((const unsigned int*)(sm + OFF_M2))[i*32 + lane]);
            as0 = fma2(dup2(wm.x), x2[0], as0);
            as1 = fma2(dup2(wm.y), x2[0], as1);
        }

        // fused scalar loops: out_mv comp-0 (WS2M) + out_s scalar part (WS2S)
        #pragma unroll 4
        for (int s2i = 0; s2i < 32; ++s2i){
            ulonglong2 sv = *(const ulonglong2*)(ss + s2i*4);
            float2 wm2 = h2f(((const unsigned int*)(sm + OFF_WS2M))[s2i*32 + lane]);
            ao[0] = fma2(dup2(wm2.x), sv.x, ao[0]);
            ao[0] = fma2(dup2(wm2.y), sv.y, ao[0]);
            uint2 u = ((const uint2*)(sm + OFF_WS2S))[s2i*32 + lane];
            float2 w01 = h2f(u.x);
            float2 w23 = h2f(u.y);
            as0 = fma2(dup2(w01.x), sv.x, as0);
            as1 = fma2(dup2(w01.y), sv.x, as1);
            as0 = fma2(dup2(w23.x), sv.y, as0);
            as1 = fma2(dup2(w23.y), sv.y, as1);
        }

        // store out_mv
        {
            float v0[16], v1[16];
            #pragma unroll
            for (int j = 0; j < 16; ++j) unpk2(ao[j], v0[j], v1[j]);
            float* op0 = out + ((size_t)p0*32 + lane)*16;
            float* op1 = op0 + 512;
            #pragma unroll
            for (int j = 0; j < 16; j += 4){
                *(float4*)(op0 + j) = make_float4(v0[j], v0[j+1], v0[j+2], v0[j+3]);
                *(float4*)(op1 + j) = make_float4(v1[j], v1[j+1], v1[j+2], v1[j+3]);
            }
        }
        // store out_s
        {
            float a0, a1, b0, b1;
            unpk2(as0, a0, a1);
            unpk2(as1, b0, b1);
            outs[(size_t)p0*64 + lane]          = a0;
            outs[(size_t)(p0+1)*64 + lane]      = a1;
            outs[(size_t)p0*64 + 32 + lane]     = b0;
            outs[(size_t)(p0+1)*64 + 32 + lane] = b1;
        }
    }
}

extern "C" void kernel_launch(void* const* d_in, const int* in_sizes, int n_in,
                              void* d_out, int out_size)
{
    const float* mv    = (const float*)d_in[0];
    const float* refmv = (const float*)d_in[1];
    const float* sc    = (const float*)d_in[2];
    const float* wLmv  = (const float*)d_in[6];
    const float* wLs   = (const float*)d_in[7];
    const float* wRmv  = (const float*)d_in[8];
    const float* wRs   = (const float*)d_in[9];
    const float* wJLmv = (const float*)d_in[10];
    const float* wJLs  = (const float*)d_in[11];
    const float* wJRmv = (const float*)d_in[12];
    const float* wJRs  = (const float*)d_in[13];
    const float* wOmv  = (const float*)d_in[14];
    const float* wOs2m = (const float*)d_in[15];
    const float* wM2s  = (const float*)d_in[16];
    const float* wS2s  = (const float*)d_in[17];
    float* out = (float*)d_out;

    const int P = in_sizes[0] / 512;
    const int pairs = P / 2;

    int sms = 148;
    cudaDeviceGetAttribute(&sms, cudaDevAttrMultiProcessorCount, 0);

    const size_t smem = (size_t)SMEMF * sizeof(float);
    cudaFuncSetAttribute(fused_kernel, cudaFuncAttributeMaxDynamicSharedMemorySize, (int)smem);

    fused_kernel<<<sms, NTHR, smem>>>(mv, refmv, sc,
                                      wLmv, wLs, wRmv, wRs,
                                      wJLmv, wJLs, wJRmv, wJRs,
                                      wOmv, wOs2m, wM2s, wS2s,
                                      out, pairs, P);
}